// round 7
// baseline (speedup 1.0000x reference)
#include <cuda_runtime.h>
#include <cuda_bf16.h>
#include <cuda_fp16.h>
#include <cstdint>
#include <math.h>

#define NN 8192
#define DD 256
#define UU 128

// ================= device scratch (no allocations allowed) =================
__device__ __align__(256) float          g_buf[NN * UU];     // stage1: u = feat@W
__device__ __align__(256) __half         g_xh[NN * UU];      // fp16 split of x (node-major)
__device__ __align__(256) __half         g_xl[NN * UU];
__device__ __align__(256) __nv_bfloat16  g_xTh[UU * NN];     // bf16 split of x, transposed
__device__ __align__(256) __nv_bfloat16  g_xTl[UU * NN];
__device__ __align__(256) float          g_x2[NN];
__device__ __align__(256) unsigned int   g_w[(size_t)NN * NN];   // packed (w_hi | w_lo<<16) bf16
__device__ __align__(256) uint32_t       g_adjb[(size_t)NN * NN / 32]; // adjacency bitmask
__device__ __align__(256) float          g_rsump[NN * 8];         // per (i, j-quarter) sums
__device__ __align__(256) float          g_mx2[2 * NN * UU];      // ksplit halves of mx

// ======================= helpers =======================
__device__ __forceinline__ uint32_t smem_to_u32(const void* p) {
    uint32_t a;
    asm("{ .reg .u64 t; cvta.to.shared.u64 t, %1; cvt.u32.u64 %0, t; }"
        : "=r"(a) : "l"(p));
    return a;
}
__device__ __forceinline__ void cp16(uint32_t saddr, const void* gaddr) {
    asm volatile("cp.async.cg.shared.global [%0], [%1], 16;"
                 :: "r"(saddr), "l"(gaddr));
}
#define CP_COMMIT() asm volatile("cp.async.commit_group;" ::: "memory")
#define CP_WAIT0()  asm volatile("cp.async.wait_group 0;" ::: "memory")

__device__ __forceinline__ void ldsm4(uint32_t& r0, uint32_t& r1, uint32_t& r2,
                                      uint32_t& r3, uint32_t addr) {
    asm volatile("ldmatrix.sync.aligned.m8n8.x4.shared.b16 {%0,%1,%2,%3}, [%4];"
                 : "=r"(r0), "=r"(r1), "=r"(r2), "=r"(r3) : "r"(addr));
}
__device__ __forceinline__ void mma_f16(float* d, const uint32_t* a,
                                        uint32_t b0, uint32_t b1) {
    asm volatile("mma.sync.aligned.m16n8k16.row.col.f32.f16.f16.f32 "
                 "{%0,%1,%2,%3}, {%4,%5,%6,%7}, {%8,%9}, {%0,%1,%2,%3};"
                 : "+f"(d[0]), "+f"(d[1]), "+f"(d[2]), "+f"(d[3])
                 : "r"(a[0]), "r"(a[1]), "r"(a[2]), "r"(a[3]), "r"(b0), "r"(b1));
}
__device__ __forceinline__ void mma_bf16(float* d, const uint32_t* a,
                                         uint32_t b0, uint32_t b1) {
    asm volatile("mma.sync.aligned.m16n8k16.row.col.f32.bf16.bf16.f32 "
                 "{%0,%1,%2,%3}, {%4,%5,%6,%7}, {%8,%9}, {%0,%1,%2,%3};"
                 : "+f"(d[0]), "+f"(d[1]), "+f"(d[2]), "+f"(d[3])
                 : "r"(a[0]), "r"(a[1]), "r"(a[2]), "r"(a[3]), "r"(b0), "r"(b1));
}
__device__ __forceinline__ float fsqrt_fast(float x) {
    float r;
    asm("sqrt.approx.f32 %0, %1;" : "=f"(r) : "f"(x));
    return r;
}

__device__ __forceinline__ float blockReduce128(float v, volatile float* sm) {
    #pragma unroll
    for (int o = 16; o > 0; o >>= 1) v += __shfl_xor_sync(0xffffffffu, v, o);
    if ((threadIdx.x & 31) == 0) sm[threadIdx.x >> 5] = v;
    __syncthreads();
    float r = sm[0] + sm[1] + sm[2] + sm[3];
    __syncthreads();
    return r;
}

// w = exp(hyperbolic distance), closed form; masked by adjacency / dist==0
// fast-math: sqrt.approx + MUFU.RCP divide (rel err ~1e-6 on w)
__device__ __forceinline__ float score_w(float xy, float x2i, float x2j, int am) {
    float A = 1.f - 2.f * xy + x2j;
    float B = 1.f - x2i;
    float num = fmaf(A * A, x2i, fmaf(-2.f * A * B, xy, B * B * x2j));
    num = fmaxf(num, 0.f);
    float den = fmaxf(fmaf(x2i, x2j, 1.f - 2.f * xy), 1e-15f);
    float sq  = fsqrt_fast(num);
    float w;
    if (sq < (1.f - 1e-7f) * den) w = __fdividef(den + sq, den - sq);
    else                          w = (2.f - 1e-7f) / 1e-7f;
    if (am == 0 || !(sq > 0.f)) w = 0.f;
    return w;
}
__device__ __forceinline__ unsigned pack_w(float w) {
    __nv_bfloat16 bh = __float2bfloat16(w);
    __nv_bfloat16 bl = __float2bfloat16(w - __bfloat162float(bh));
    return (unsigned)__bfloat16_as_ushort(bh) |
           ((unsigned)__bfloat16_as_ushort(bl) << 16);
}

// ============================================================
// Stage 0: adjacency -> bitmask (1 thread per 32 ints)
// ============================================================
__global__ __launch_bounds__(256) void k_adjmask(const int* __restrict__ adj) {
    size_t w = (size_t)blockIdx.x * 256 + threadIdx.x;
    const int4* p = (const int4*)(adj + w * 32);
    uint32_t m = 0;
    #pragma unroll
    for (int q = 0; q < 8; q++) {
        int4 v = p[q];
        m |= (v.x != 0 ? 1u : 0u) << (q * 4 + 0);
        m |= (v.y != 0 ? 1u : 0u) << (q * 4 + 1);
        m |= (v.z != 0 ? 1u : 0u) << (q * 4 + 2);
        m |= (v.w != 0 ? 1u : 0u) << (q * 4 + 3);
    }
    g_adjb[w] = m;
}

// ============================================================
// Stage 1: u = features @ kernel
// ============================================================
__global__ __launch_bounds__(256) void k_gemmA(const float* __restrict__ feat,
                                               const float* __restrict__ W) {
    __shared__ float fs[16][DD];
    int tid = threadIdx.x;
    int r0  = blockIdx.x * 16;
    for (int idx = tid; idx < 16 * DD; idx += 256)
        fs[idx >> 8][idx & 255] = feat[(size_t)(r0 + (idx >> 8)) * DD + (idx & 255)];
    __syncthreads();
    int col = tid & 127, rg = tid >> 7;
    float acc[8] = {0.f,0.f,0.f,0.f,0.f,0.f,0.f,0.f};
    for (int d = 0; d < DD; d++) {
        float kv = W[d * UU + col];
        #pragma unroll
        for (int r = 0; r < 8; r++)
            acc[r] = fmaf(fs[rg * 8 + r][d], kv, acc[r]);
    }
    #pragma unroll
    for (int r = 0; r < 8; r++)
        g_buf[(size_t)(r0 + rg * 8 + r) * UU + col] = acc[r];
}

// ============================================================
// Stage 2: x = expmap0(u); fp16 split, bf16 transposed split, x2
// ============================================================
__global__ __launch_bounds__(128) void k_expmap() {
    __shared__ float sm[4];
    int row = blockIdx.x, t = threadIdx.x;
    float v  = g_buf[(size_t)row * UU + t];
    float n2 = blockReduce128(v * v, sm);
    float n  = fmaxf(sqrtf(n2), 1e-15f);
    float xv = tanhf(n) / n * v;

    __half hh = __float2half(xv);
    __half hl = __float2half(xv - __half2float(hh));
    g_xh[(size_t)row * UU + t] = hh;
    g_xl[(size_t)row * UU + t] = hl;

    __nv_bfloat16 bh = __float2bfloat16(xv);
    __nv_bfloat16 bl = __float2bfloat16(xv - __bfloat162float(bh));
    g_xTh[(size_t)t * NN + row] = bh;
    g_xTl[(size_t)t * NN + row] = bl;

    float s2 = blockReduce128(xv * xv, sm);
    if (t == 0) g_x2[row] = s2;
}

// ============================================================
// Stage 3 (k_attn): persistent, cp.async double-buffered, 512 threads.
// grid 512 = 64 ib x 8 jq; warp grid 8(m16) x 2(n64).
// smem: [Ahi][Alo][Bhi0][Blo0][Bhi1][Blo1] + rsum combine area.
// ============================================================
#define SKA 136
#define ATILE (128 * SKA * 2)          /* 34816 B */
#define RS_OFF (6 * ATILE)
#define G1_SMEM (6 * ATILE + 1024)

__device__ __forceinline__ void cp_tile16_512(char* dst, const __half* src,
                                              int r0, int tid) {
    #pragma unroll
    for (int it = 0; it < 4; it++) {
        int idx = it * 512 + tid;
        int row = idx >> 4, q = idx & 15;
        cp16(smem_to_u32(dst + (row * SKA + q * 8) * 2),
             (const void*)(src + (size_t)(r0 + row) * UU + q * 8));
    }
}

__global__ __launch_bounds__(512) void k_attn() {
    extern __shared__ char smc[];
    uint32_t sb = smem_to_u32(smc);
    int tid = threadIdx.x, wid = tid >> 5, lane = tid & 31;
    int ib = blockIdx.x >> 3, jq = blockIdx.x & 7;
    int i0 = ib * 128;

    int wm = (wid & 7) * 16, wn = (wid >> 3) * 64;
    int g = lane >> 2, tq = lane & 3;
    int aRow = (lane & 7) + ((lane >> 3) & 1) * 8;
    int aCol = (lane >> 4) * 8;
    int bRow = (lane & 7) + (lane >> 4) * 8;
    int bCol = ((lane >> 3) & 1) * 8;

    // prologue: A hi/lo resident + B(c=0) hi/lo
    cp_tile16_512(smc + 0 * ATILE, g_xh, i0, tid);
    cp_tile16_512(smc + 1 * ATILE, g_xl, i0, tid);
    cp_tile16_512(smc + 2 * ATILE, g_xh, jq * 1024, tid);
    cp_tile16_512(smc + 3 * ATILE, g_xl, jq * 1024, tid);
    CP_COMMIT();

    float x2i[2];
    x2i[0] = g_x2[i0 + wm + g];
    x2i[1] = g_x2[i0 + wm + g + 8];

    float rsum[2] = {0.f, 0.f};

    CP_WAIT0();
    __syncthreads();

    for (int c = 0; c < 8; c++) {
        int s = c & 1;
        if (c < 7) {   // prefetch next j-tile into the other stage
            int jn = jq * 1024 + (c + 1) * 128;
            cp_tile16_512(smc + (2 + 2 * (s ^ 1)) * ATILE, g_xh, jn, tid);
            cp_tile16_512(smc + (3 + 2 * (s ^ 1)) * ATILE, g_xl, jn, tid);
            CP_COMMIT();
        }

        // ---- MMA: 3 products (hi*hi + hi*lo + lo*hi) ----
        float acc[8][4];
        #pragma unroll
        for (int nb = 0; nb < 8; nb++)
            #pragma unroll
            for (int q = 0; q < 4; q++) acc[nb][q] = 0.f;

        #pragma unroll
        for (int p = 0; p < 3; p++) {
            uint32_t Ab = sb + (p == 2 ? ATILE : 0);
            uint32_t Bb = sb + (uint32_t)(2 + 2 * s + (p == 1 ? 1 : 0)) * ATILE;
            #pragma unroll
            for (int ksv = 0; ksv < 8; ksv++) {
                int k0 = ksv * 16;
                uint32_t a[4], b[4][4];
                ldsm4(a[0], a[1], a[2], a[3],
                      Ab + (uint32_t)((wm + aRow) * SKA + k0 + aCol) * 2);
                #pragma unroll
                for (int nb = 0; nb < 4; nb++)
                    ldsm4(b[nb][0], b[nb][1], b[nb][2], b[nb][3],
                          Bb + (uint32_t)((wn + nb * 16 + bRow) * SKA + k0 + bCol) * 2);
                #pragma unroll
                for (int nb = 0; nb < 4; nb++) {
                    mma_f16(acc[2 * nb],     a, b[nb][0], b[nb][1]);
                    mma_f16(acc[2 * nb + 1], a, b[nb][2], b[nb][3]);
                }
            }
        }

        // ---- score epilogue straight from accumulators ----
        int j0c = jq * 1024 + c * 128;
        #pragma unroll
        for (int rh = 0; rh < 2; rh++) {
            int ig = i0 + wm + g + rh * 8;
            uint2 mwv = *(const uint2*)&g_adjb[(size_t)ig * (NN / 32)
                                               + ((j0c + wn) >> 5)];
            float x2iv = x2i[rh];
            float rs = 0.f;
            #pragma unroll
            for (int nbi = 0; nbi < 8; nbi++) {
                int jl = wn + nbi * 8 + 2 * tq;
                int jg = j0c + jl;
                float2 x2jv = *(const float2*)&g_x2[jg];
                uint32_t mword = (nbi < 4) ? mwv.x : mwv.y;
                int sh = jl & 31;
                int a0 = (mword >> sh) & 1;
                int a1 = (mword >> (sh + 1)) & 1;
                float w0 = score_w(acc[nbi][rh * 2 + 0], x2iv, x2jv.x, a0);
                float w1 = score_w(acc[nbi][rh * 2 + 1], x2iv, x2jv.y, a1);
                *(uint2*)&g_w[(size_t)ig * NN + jg] =
                    make_uint2(pack_w(w0), pack_w(w1));
                rs += w0 + w1;
            }
            rsum[rh] += rs;
        }

        if (c < 7) CP_WAIT0();
        __syncthreads();
    }

    // ---- row-sum combine: reduce over tq, then warp pairs ----
    #pragma unroll
    for (int r = 0; r < 2; r++) {
        rsum[r] += __shfl_xor_sync(0xffffffffu, rsum[r], 1);
        rsum[r] += __shfl_xor_sync(0xffffffffu, rsum[r], 2);
    }
    float* RS = (float*)(smc + RS_OFF);    // [16 warps][16 rows]
    if (tq == 0) {
        RS[wid * 16 + g]     = rsum[0];
        RS[wid * 16 + 8 + g] = rsum[1];
    }
    __syncthreads();
    if (tid < 128) {
        int mt = tid >> 4, idx = tid & 15;
        float v = RS[mt * 16 + idx] + RS[(mt + 8) * 16 + idx];
        g_rsump[(i0 + tid) * 8 + jq] = v;
    }
}

// ============================================================
// Stage 4 (k_agg): mx = W @ X, bf16-split HMMA, 512 threads.
// grid 128 (64 i-tiles x ksplit 2), 64-j chunks, double buffer.
// stage layout: [Whi][Wlo][Xhi][Xlo], each 128 x SKC bf16.
// ============================================================
#define SKC 72
#define CT  (128 * SKC * 2)        /* 18432 B */
#define STG (4 * CT)               /* 73728 B */
#define G2_SMEM (2 * STG)          /* 147456 B */

__global__ __launch_bounds__(512) void k_agg() {
    extern __shared__ char smc[];
    uint32_t sb = smem_to_u32(smc);
    int tid = threadIdx.x, wid = tid >> 5, lane = tid & 31;
    int ib = blockIdx.x >> 1, ks = blockIdx.x & 1;
    int i0 = ib * 128, jbeg = ks * 4096;

    int wm = (wid & 7) * 16, wn = (wid >> 3) * 64;
    int aRow = (lane & 7) + ((lane >> 3) & 1) * 8;
    int aCol = (lane >> 4) * 8;
    int bRow = (lane & 7) + (lane >> 4) * 8;
    int bCol = ((lane >> 3) & 1) * 8;

    float acc[8][4];
    #pragma unroll
    for (int nb = 0; nb < 8; nb++)
        #pragma unroll
        for (int q = 0; q < 4; q++) acc[nb][q] = 0.f;

    // ---- X^T cp.async loader (512 threads) ----
    #define CP_X(cc, ss) do {                                                  \
        int jc0 = jbeg + (cc) * 64;                                            \
        char* st = smc + (ss) * STG;                                           \
        _Pragma("unroll")                                                      \
        for (int it = 0; it < 2; it++) {                                       \
            int idx = it * 512 + tid;                                          \
            int row = idx >> 3, q = idx & 7;                                   \
            int off = (row * SKC + q * 8) * 2;                                 \
            cp16(smem_to_u32(st + 2 * CT + off),                               \
                 (const void*)(g_xTh + (size_t)row * NN + jc0 + q * 8));       \
            cp16(smem_to_u32(st + 3 * CT + off),                               \
                 (const void*)(g_xTl + (size_t)row * NN + jc0 + q * 8));       \
        }                                                                      \
    } while (0)

    // ---- W loaders: LDG to regs / perm+STS from regs ----
    #define LDG_W(cc, vreg) do {                                               \
        int jc0 = jbeg + (cc) * 64;                                            \
        _Pragma("unroll")                                                      \
        for (int it = 0; it < 4; it++) {                                       \
            int idx = it * 512 + tid;                                          \
            int row = idx >> 4, q = idx & 15;                                  \
            (vreg)[it] = *(const uint4*)(g_w + (size_t)(i0 + row) * NN         \
                                         + jc0 + q * 4);                       \
        }                                                                      \
    } while (0)
    #define STS_W(ss, vreg) do {                                               \
        char* st = smc + (ss) * STG;                                           \
        _Pragma("unroll")                                                      \
        for (int it = 0; it < 4; it++) {                                       \
            int idx = it * 512 + tid;                                          \
            int row = idx >> 4, q = idx & 15;                                  \
            unsigned h01 = __byte_perm((vreg)[it].x, (vreg)[it].y, 0x5410);    \
            unsigned h23 = __byte_perm((vreg)[it].z, (vreg)[it].w, 0x5410);    \
            unsigned l01 = __byte_perm((vreg)[it].x, (vreg)[it].y, 0x7632);    \
            unsigned l23 = __byte_perm((vreg)[it].z, (vreg)[it].w, 0x7632);    \
            int off = (row * SKC + q * 4) * 2;                                 \
            *(uint2*)(st + off)      = make_uint2(h01, h23);                   \
            *(uint2*)(st + CT + off) = make_uint2(l01, l23);                   \
        }                                                                      \
    } while (0)

    // prologue: chunk 0
    uint4 vW[4];
    CP_X(0, 0);
    CP_COMMIT();
    LDG_W(0, vW);
    STS_W(0, vW);
    CP_WAIT0();
    __syncthreads();

    for (int c = 0; c < 64; c++) {
        int s = c & 1;
        if (c < 63) {
            CP_X(c + 1, s ^ 1);
            CP_COMMIT();
            LDG_W(c + 1, vW);     // LDG latency hidden behind MMAs below
        }

        uint32_t stb = sb + s * STG;
        #pragma unroll
        for (int p = 0; p < 3; p++) {
            uint32_t Ab = stb + (p == 2 ? CT : 0);            // W: hi, hi, lo
            uint32_t Bb = stb + 2 * CT + (p == 1 ? CT : 0);   // X: hi, lo, hi
            #pragma unroll
            for (int ksv = 0; ksv < 4; ksv++) {
                int k0 = ksv * 16;
                uint32_t a[4], b[4][4];
                ldsm4(a[0], a[1], a[2], a[3],
                      Ab + (uint32_t)((wm + aRow) * SKC + k0 + aCol) * 2);
                #pragma unroll
                for (int nb = 0; nb < 4; nb++)
                    ldsm4(b[nb][0], b[nb][1], b[nb][2], b[nb][3],
                          Bb + (uint32_t)((wn + nb * 16 + bRow) * SKC + k0 + bCol) * 2);
                #pragma unroll
                for (int nb = 0; nb < 4; nb++) {
                    mma_bf16(acc[2 * nb],     a, b[nb][0], b[nb][1]);
                    mma_bf16(acc[2 * nb + 1], a, b[nb][2], b[nb][3]);
                }
            }
        }

        if (c < 63) STS_W(s ^ 1, vW);
        CP_WAIT0();
        __syncthreads();
    }

    // ---- writeback (each (i,d) owned by exactly one CTA per ksplit half) ----
    int g = lane >> 2, tq = lane & 3;
    #pragma unroll
    for (int nbi = 0; nbi < 8; nbi++) {
        int irow = i0 + wm + g;
        int dcol = wn + nbi * 8 + 2 * tq;
        *(float2*)&g_mx2[((size_t)ks * NN + irow) * UU + dcol] =
            make_float2(acc[nbi][0], acc[nbi][1]);
        *(float2*)&g_mx2[((size_t)ks * NN + irow + 8) * UU + dcol] =
            make_float2(acc[nbi][2], acc[nbi][3]);
    }
}

// ============================================================
// Stage 5: combine halves, normalize, hyperbolic rescale + mobius bias add
// ============================================================
__global__ __launch_bounds__(128) void k_epilogue(const float* __restrict__ bias,
                                                  float* __restrict__ out) {
    __shared__ float sm[4];
    int row = blockIdx.x, t = threadIdx.x;

    float rp = (t < 8) ? g_rsump[row * 8 + t] : 0.f;
    float rs = blockReduce128(rp, sm);

    float m = __fdividef(g_mx2[(size_t)row * UU + t] +
                         g_mx2[(size_t)(NN + row) * UU + t], rs);
    float mn2 = blockReduce128(m * m, sm);
    float x2i = g_x2[row];
    float x_n  = fmaxf(sqrtf(x2i), 1e-15f);
    float mx_n = fmaxf(sqrtf(mn2), 1e-15f);
    float xa   = fminf(x_n, 1.f - 1e-7f);
    float art  = 0.5f * (log1pf(xa) - log1pf(-xa));
    float alpha = __fdividef(tanhf(__fdividef(mx_n, x_n) * art), mx_n);
    float ov = alpha * m;

    float bv  = bias[t];
    float bn2 = blockReduce128(bv * bv, sm);
    float bn  = fmaxf(sqrtf(bn2), 1e-15f);
    float bvx = __fdividef(tanhf(bn), bn) * bv;

    float y2  = blockReduce128(bvx * bvx, sm);
    float xy  = blockReduce128(ov * bvx, sm);
    float x2o = blockReduce128(ov * ov, sm);
    float cx  = 1.f + 2.f * xy + y2;
    float cy  = 1.f - x2o;
    float den = fmaxf(fmaf(x2o, y2, 1.f + 2.f * xy), 1e-15f);
    out[(size_t)row * UU + t] = __fdividef(cx * ov + cy * bvx, den);
}

// ============================================================
extern "C" void kernel_launch(void* const* d_in, const int* in_sizes, int n_in,
                              void* d_out, int out_size) {
    const float* feat = (const float*)d_in[0];
    const int*   adj  = (const int*)  d_in[1];
    const float* W    = (const float*)d_in[2];
    const float* bias = (const float*)d_in[3];
    float* out = (float*)d_out;

    cudaFuncSetAttribute(k_attn, cudaFuncAttributeMaxDynamicSharedMemorySize, G1_SMEM);
    cudaFuncSetAttribute(k_agg,  cudaFuncAttributeMaxDynamicSharedMemorySize, G2_SMEM);

    k_adjmask <<<NN * NN / 32 / 256, 256>>>(adj);
    k_gemmA   <<<NN / 16, 256>>>(feat, W);
    k_expmap  <<<NN, 128>>>();
    k_attn    <<<512, 512, G1_SMEM>>>();
    k_agg     <<<128, 512, G2_SMEM>>>();
    k_epilogue<<<NN, 128>>>(bias, out);
}

// round 8
// speedup vs baseline: 1.3438x; 1.3438x over previous
#include <cuda_runtime.h>
#include <cuda_bf16.h>
#include <cuda_fp16.h>
#include <cstdint>
#include <math.h>

#define NN 8192
#define DD 256
#define UU 128

// ================= device scratch (no allocations allowed) =================
__device__ __align__(256) float          g_buf[NN * UU];     // stage1: u = feat@W
__device__ __align__(256) __half         g_xh[NN * UU];      // fp16 split of x (node-major)
__device__ __align__(256) __half         g_xl[NN * UU];
__device__ __align__(256) __nv_bfloat16  g_xTh[UU * NN];     // bf16 split of x, transposed
__device__ __align__(256) __nv_bfloat16  g_xTl[UU * NN];
__device__ __align__(256) float          g_x2[NN];
__device__ __align__(256) unsigned int   g_w[(size_t)NN * NN];   // packed (w_hi | w_lo<<16) bf16
__device__ __align__(256) uint32_t       g_adjb[(size_t)NN * NN / 32]; // adjacency bitmask
__device__ __align__(256) float          g_rsump[NN * 8];         // per (i, j-quarter) sums
__device__ __align__(256) float          g_mx2[2 * NN * UU];      // ksplit halves of mx

// ======================= helpers =======================
__device__ __forceinline__ uint32_t smem_to_u32(const void* p) {
    uint32_t a;
    asm("{ .reg .u64 t; cvta.to.shared.u64 t, %1; cvt.u32.u64 %0, t; }"
        : "=r"(a) : "l"(p));
    return a;
}
__device__ __forceinline__ void cp16(uint32_t saddr, const void* gaddr) {
    asm volatile("cp.async.cg.shared.global [%0], [%1], 16;"
                 :: "r"(saddr), "l"(gaddr));
}
#define CP_COMMIT() asm volatile("cp.async.commit_group;" ::: "memory")
#define CP_WAIT0()  asm volatile("cp.async.wait_group 0;" ::: "memory")

__device__ __forceinline__ void ldsm4(uint32_t& r0, uint32_t& r1, uint32_t& r2,
                                      uint32_t& r3, uint32_t addr) {
    asm volatile("ldmatrix.sync.aligned.m8n8.x4.shared.b16 {%0,%1,%2,%3}, [%4];"
                 : "=r"(r0), "=r"(r1), "=r"(r2), "=r"(r3) : "r"(addr));
}
__device__ __forceinline__ void mma_f16(float* d, const uint32_t* a,
                                        uint32_t b0, uint32_t b1) {
    asm volatile("mma.sync.aligned.m16n8k16.row.col.f32.f16.f16.f32 "
                 "{%0,%1,%2,%3}, {%4,%5,%6,%7}, {%8,%9}, {%0,%1,%2,%3};"
                 : "+f"(d[0]), "+f"(d[1]), "+f"(d[2]), "+f"(d[3])
                 : "r"(a[0]), "r"(a[1]), "r"(a[2]), "r"(a[3]), "r"(b0), "r"(b1));
}
__device__ __forceinline__ void mma_bf16(float* d, const uint32_t* a,
                                         uint32_t b0, uint32_t b1) {
    asm volatile("mma.sync.aligned.m16n8k16.row.col.f32.bf16.bf16.f32 "
                 "{%0,%1,%2,%3}, {%4,%5,%6,%7}, {%8,%9}, {%0,%1,%2,%3};"
                 : "+f"(d[0]), "+f"(d[1]), "+f"(d[2]), "+f"(d[3])
                 : "r"(a[0]), "r"(a[1]), "r"(a[2]), "r"(a[3]), "r"(b0), "r"(b1));
}
__device__ __forceinline__ float fsqrt_fast(float x) {
    float r;
    asm("sqrt.approx.f32 %0, %1;" : "=f"(r) : "f"(x));
    return r;
}

__device__ __forceinline__ float blockReduce128(float v, volatile float* sm) {
    #pragma unroll
    for (int o = 16; o > 0; o >>= 1) v += __shfl_xor_sync(0xffffffffu, v, o);
    if ((threadIdx.x & 31) == 0) sm[threadIdx.x >> 5] = v;
    __syncthreads();
    float r = sm[0] + sm[1] + sm[2] + sm[3];
    __syncthreads();
    return r;
}

// w = exp(hyperbolic distance), closed form; masked by adjacency / dist==0
__device__ __forceinline__ float score_w(float xy, float x2i, float x2j, int am) {
    float A = 1.f - 2.f * xy + x2j;
    float B = 1.f - x2i;
    float num = fmaf(A * A, x2i, fmaf(-2.f * A * B, xy, B * B * x2j));
    num = fmaxf(num, 0.f);
    float den = fmaxf(fmaf(x2i, x2j, 1.f - 2.f * xy), 1e-15f);
    float sq  = fsqrt_fast(num);
    float w;
    if (sq < (1.f - 1e-7f) * den) w = __fdividef(den + sq, den - sq);
    else                          w = (2.f - 1e-7f) / 1e-7f;
    if (am == 0 || !(sq > 0.f)) w = 0.f;
    return w;
}
__device__ __forceinline__ unsigned pack_w(float w) {
    __nv_bfloat16 bh = __float2bfloat16(w);
    __nv_bfloat16 bl = __float2bfloat16(w - __bfloat162float(bh));
    return (unsigned)__bfloat16_as_ushort(bh) |
           ((unsigned)__bfloat16_as_ushort(bl) << 16);
}

// ============================================================
// Stage 0: adjacency -> bitmask (1 thread per 32 ints)
// ============================================================
__global__ __launch_bounds__(256) void k_adjmask(const int* __restrict__ adj) {
    size_t w = (size_t)blockIdx.x * 256 + threadIdx.x;
    const int4* p = (const int4*)(adj + w * 32);
    uint32_t m = 0;
    #pragma unroll
    for (int q = 0; q < 8; q++) {
        int4 v = p[q];
        m |= (v.x != 0 ? 1u : 0u) << (q * 4 + 0);
        m |= (v.y != 0 ? 1u : 0u) << (q * 4 + 1);
        m |= (v.z != 0 ? 1u : 0u) << (q * 4 + 2);
        m |= (v.w != 0 ? 1u : 0u) << (q * 4 + 3);
    }
    g_adjb[w] = m;
}

// ============================================================
// Stage 1: u = features @ kernel
// ============================================================
__global__ __launch_bounds__(256) void k_gemmA(const float* __restrict__ feat,
                                               const float* __restrict__ W) {
    __shared__ float fs[16][DD];
    int tid = threadIdx.x;
    int r0  = blockIdx.x * 16;
    for (int idx = tid; idx < 16 * DD; idx += 256)
        fs[idx >> 8][idx & 255] = feat[(size_t)(r0 + (idx >> 8)) * DD + (idx & 255)];
    __syncthreads();
    int col = tid & 127, rg = tid >> 7;
    float acc[8] = {0.f,0.f,0.f,0.f,0.f,0.f,0.f,0.f};
    for (int d = 0; d < DD; d++) {
        float kv = W[d * UU + col];
        #pragma unroll
        for (int r = 0; r < 8; r++)
            acc[r] = fmaf(fs[rg * 8 + r][d], kv, acc[r]);
    }
    #pragma unroll
    for (int r = 0; r < 8; r++)
        g_buf[(size_t)(r0 + rg * 8 + r) * UU + col] = acc[r];
}

// ============================================================
// Stage 2: x = expmap0(u); fp16 split, bf16 transposed split, x2
// ============================================================
__global__ __launch_bounds__(128) void k_expmap() {
    __shared__ float sm[4];
    int row = blockIdx.x, t = threadIdx.x;
    float v  = g_buf[(size_t)row * UU + t];
    float n2 = blockReduce128(v * v, sm);
    float n  = fmaxf(sqrtf(n2), 1e-15f);
    float xv = tanhf(n) / n * v;

    __half hh = __float2half(xv);
    __half hl = __float2half(xv - __half2float(hh));
    g_xh[(size_t)row * UU + t] = hh;
    g_xl[(size_t)row * UU + t] = hl;

    __nv_bfloat16 bh = __float2bfloat16(xv);
    __nv_bfloat16 bl = __float2bfloat16(xv - __bfloat162float(bh));
    g_xTh[(size_t)t * NN + row] = bh;
    g_xTl[(size_t)t * NN + row] = bl;

    float s2 = blockReduce128(xv * xv, sm);
    if (t == 0) g_x2[row] = s2;
}

// ============================================================
// Stage 3 (k_attn): BM=64/BN=64 tiles, 256 threads, 105KB smem
// -> 2 CTAs/SM (two independent barrier domains).
// grid 1024 = 128 ib x 8 jq; warp grid 4(m16) x 2(n32).
// A-fragment hoisted across the 3 split products (10 ldsm/ks).
// ============================================================
#define SKA 136
#define AT64 (64 * SKA * 2)            /* 17408 B per 64-row fp16 tile */
#define RS_OFF (6 * AT64)
#define G1_SMEM (6 * AT64 + 512)       /* 104960 B */

__device__ __forceinline__ void cp_tile64(char* dst, const __half* src,
                                          int r0, int tid) {
    #pragma unroll
    for (int it = 0; it < 4; it++) {
        int idx = it * 256 + tid;
        int row = idx >> 4, q = idx & 15;
        cp16(smem_to_u32(dst + (row * SKA + q * 8) * 2),
             (const void*)(src + (size_t)(r0 + row) * UU + q * 8));
    }
}

__global__ __launch_bounds__(256) void k_attn() {
    extern __shared__ char smc[];
    uint32_t sb = smem_to_u32(smc);
    int tid = threadIdx.x, wid = tid >> 5, lane = tid & 31;
    int ib = blockIdx.x >> 3, jq = blockIdx.x & 7;
    int i0 = ib * 64;

    int wm = (wid & 3) * 16, wn = (wid >> 2) * 32;
    int g = lane >> 2, tq = lane & 3;
    int aRow = (lane & 7) + ((lane >> 3) & 1) * 8;
    int aCol = (lane >> 4) * 8;
    int bRow = (lane & 7) + (lane >> 4) * 8;
    int bCol = ((lane >> 3) & 1) * 8;

    // prologue: A hi/lo resident + B(c=0) hi/lo
    cp_tile64(smc + 0 * AT64, g_xh, i0, tid);
    cp_tile64(smc + 1 * AT64, g_xl, i0, tid);
    cp_tile64(smc + 2 * AT64, g_xh, jq * 1024, tid);
    cp_tile64(smc + 3 * AT64, g_xl, jq * 1024, tid);
    CP_COMMIT();

    float x2i[2];
    x2i[0] = g_x2[i0 + wm + g];
    x2i[1] = g_x2[i0 + wm + g + 8];

    float rsum[2] = {0.f, 0.f};

    CP_WAIT0();
    __syncthreads();

    for (int c = 0; c < 16; c++) {
        int s = c & 1;
        if (c < 15) {   // prefetch next 64-row j-tile into the other stage
            int jn = jq * 1024 + (c + 1) * 64;
            cp_tile64(smc + (2 + 2 * (s ^ 1)) * AT64, g_xh, jn, tid);
            cp_tile64(smc + (3 + 2 * (s ^ 1)) * AT64, g_xl, jn, tid);
            CP_COMMIT();
        }

        // ---- MMA: hoisted fragments, 3 products (hh + hl + lh) ----
        float acc[4][4];
        #pragma unroll
        for (int nb = 0; nb < 4; nb++)
            #pragma unroll
            for (int q = 0; q < 4; q++) acc[nb][q] = 0.f;

        uint32_t Ah = sb, Al = sb + AT64;
        uint32_t Bh = sb + (uint32_t)(2 + 2 * s) * AT64;
        uint32_t Bl = Bh + AT64;
        #pragma unroll
        for (int ksv = 0; ksv < 8; ksv++) {
            int k0 = ksv * 16;
            uint32_t ah[4], al[4], bh[2][4], bl[2][4];
            ldsm4(ah[0], ah[1], ah[2], ah[3],
                  Ah + (uint32_t)((wm + aRow) * SKA + k0 + aCol) * 2);
            ldsm4(al[0], al[1], al[2], al[3],
                  Al + (uint32_t)((wm + aRow) * SKA + k0 + aCol) * 2);
            #pragma unroll
            for (int nb = 0; nb < 2; nb++) {
                ldsm4(bh[nb][0], bh[nb][1], bh[nb][2], bh[nb][3],
                      Bh + (uint32_t)((wn + nb * 16 + bRow) * SKA + k0 + bCol) * 2);
                ldsm4(bl[nb][0], bl[nb][1], bl[nb][2], bl[nb][3],
                      Bl + (uint32_t)((wn + nb * 16 + bRow) * SKA + k0 + bCol) * 2);
            }
            #pragma unroll
            for (int nb = 0; nb < 2; nb++) {
                mma_f16(acc[2 * nb],     ah, bh[nb][0], bh[nb][1]);
                mma_f16(acc[2 * nb + 1], ah, bh[nb][2], bh[nb][3]);
                mma_f16(acc[2 * nb],     ah, bl[nb][0], bl[nb][1]);
                mma_f16(acc[2 * nb + 1], ah, bl[nb][2], bl[nb][3]);
                mma_f16(acc[2 * nb],     al, bh[nb][0], bh[nb][1]);
                mma_f16(acc[2 * nb + 1], al, bh[nb][2], bh[nb][3]);
            }
        }

        // ---- score epilogue straight from accumulators ----
        int jc = jq * 1024 + c * 64;
        #pragma unroll
        for (int rh = 0; rh < 2; rh++) {
            int ig = i0 + wm + g + rh * 8;
            uint32_t mword = g_adjb[(size_t)ig * (NN / 32) + ((jc + wn) >> 5)];
            float x2iv = x2i[rh];
            float rs = 0.f;
            #pragma unroll
            for (int nbi = 0; nbi < 4; nbi++) {
                int jl = nbi * 8 + 2 * tq;           // 0..30 within 32-j group
                int jg = jc + wn + jl;
                float2 x2jv = *(const float2*)&g_x2[jg];
                int a0 = (mword >> jl) & 1;
                int a1 = (mword >> (jl + 1)) & 1;
                float w0 = score_w(acc[nbi][rh * 2 + 0], x2iv, x2jv.x, a0);
                float w1 = score_w(acc[nbi][rh * 2 + 1], x2iv, x2jv.y, a1);
                *(uint2*)&g_w[(size_t)ig * NN + jg] =
                    make_uint2(pack_w(w0), pack_w(w1));
                rs += w0 + w1;
            }
            rsum[rh] += rs;
        }

        if (c < 15) CP_WAIT0();
        __syncthreads();
    }

    // ---- row-sum combine: reduce over tq, then n-group pairs ----
    #pragma unroll
    for (int r = 0; r < 2; r++) {
        rsum[r] += __shfl_xor_sync(0xffffffffu, rsum[r], 1);
        rsum[r] += __shfl_xor_sync(0xffffffffu, rsum[r], 2);
    }
    float* RS = (float*)(smc + RS_OFF);    // [8 warps][16 rows]
    if (tq == 0) {
        RS[wid * 16 + g]     = rsum[0];
        RS[wid * 16 + 8 + g] = rsum[1];
    }
    __syncthreads();
    if (tid < 64) {
        int mt = tid >> 4, idx = tid & 15;
        float v = RS[mt * 16 + idx] + RS[(mt + 4) * 16 + idx];
        g_rsump[(i0 + mt * 16 + idx) * 8 + jq] = v;
    }
}

// ============================================================
// Stage 4 (k_agg): mx = W @ X, bf16-split HMMA, 512 threads.
// grid 128 (64 i-tiles x ksplit 2), 64-j chunks, double buffer.
// stage layout: [Whi][Wlo][Xhi][Xlo], each 128 x SKC bf16.
// Fragments hoisted: 10 ldsm/ks instead of 15.
// ============================================================
#define SKC 72
#define CT  (128 * SKC * 2)        /* 18432 B */
#define STG (4 * CT)               /* 73728 B */
#define G2_SMEM (2 * STG)          /* 147456 B */

__global__ __launch_bounds__(512) void k_agg() {
    extern __shared__ char smc[];
    uint32_t sb = smem_to_u32(smc);
    int tid = threadIdx.x, wid = tid >> 5, lane = tid & 31;
    int ib = blockIdx.x >> 1, ks = blockIdx.x & 1;
    int i0 = ib * 128, jbeg = ks * 4096;

    int wm = (wid & 7) * 16, wn = (wid >> 3) * 64;
    int aRow = (lane & 7) + ((lane >> 3) & 1) * 8;
    int aCol = (lane >> 4) * 8;
    int bRow = (lane & 7) + (lane >> 4) * 8;
    int bCol = ((lane >> 3) & 1) * 8;

    float acc[8][4];
    #pragma unroll
    for (int nb = 0; nb < 8; nb++)
        #pragma unroll
        for (int q = 0; q < 4; q++) acc[nb][q] = 0.f;

    // ---- X^T cp.async loader (512 threads) ----
    #define CP_X(cc, ss) do {                                                  \
        int jc0 = jbeg + (cc) * 64;                                            \
        char* st = smc + (ss) * STG;                                           \
        _Pragma("unroll")                                                      \
        for (int it = 0; it < 2; it++) {                                       \
            int idx = it * 512 + tid;                                          \
            int row = idx >> 3, q = idx & 7;                                   \
            int off = (row * SKC + q * 8) * 2;                                 \
            cp16(smem_to_u32(st + 2 * CT + off),                               \
                 (const void*)(g_xTh + (size_t)row * NN + jc0 + q * 8));       \
            cp16(smem_to_u32(st + 3 * CT + off),                               \
                 (const void*)(g_xTl + (size_t)row * NN + jc0 + q * 8));       \
        }                                                                      \
    } while (0)

    // ---- W loaders: LDG to regs / perm+STS from regs ----
    #define LDG_W(cc, vreg) do {                                               \
        int jc0 = jbeg + (cc) * 64;                                            \
        _Pragma("unroll")                                                      \
        for (int it = 0; it < 4; it++) {                                       \
            int idx = it * 512 + tid;                                          \
            int row = idx >> 4, q = idx & 15;                                  \
            (vreg)[it] = *(const uint4*)(g_w + (size_t)(i0 + row) * NN         \
                                         + jc0 + q * 4);                       \
        }                                                                      \
    } while (0)
    #define STS_W(ss, vreg) do {                                               \
        char* st = smc + (ss) * STG;                                           \
        _Pragma("unroll")                                                      \
        for (int it = 0; it < 4; it++) {                                       \
            int idx = it * 512 + tid;                                          \
            int row = idx >> 4, q = idx & 15;                                  \
            unsigned h01 = __byte_perm((vreg)[it].x, (vreg)[it].y, 0x5410);    \
            unsigned h23 = __byte_perm((vreg)[it].z, (vreg)[it].w, 0x5410);    \
            unsigned l01 = __byte_perm((vreg)[it].x, (vreg)[it].y, 0x7632);    \
            unsigned l23 = __byte_perm((vreg)[it].z, (vreg)[it].w, 0x7632);    \
            int off = (row * SKC + q * 4) * 2;                                 \
            *(uint2*)(st + off)      = make_uint2(h01, h23);                   \
            *(uint2*)(st + CT + off) = make_uint2(l01, l23);                   \
        }                                                                      \
    } while (0)

    // prologue: chunk 0
    uint4 vW[4];
    CP_X(0, 0);
    CP_COMMIT();
    LDG_W(0, vW);
    STS_W(0, vW);
    CP_WAIT0();
    __syncthreads();

    for (int c = 0; c < 64; c++) {
        int s = c & 1;
        if (c < 63) {
            CP_X(c + 1, s ^ 1);
            CP_COMMIT();
            LDG_W(c + 1, vW);     // LDG latency hidden behind MMAs below
        }

        uint32_t stb = sb + s * STG;
        uint32_t Wh = stb, Wl = stb + CT;
        uint32_t Xh = stb + 2 * CT, Xl = stb + 3 * CT;
        #pragma unroll
        for (int ksv = 0; ksv < 4; ksv++) {
            int k0 = ksv * 16;
            uint32_t ah[4], al[4], bh[4][4], bl[4][4];
            ldsm4(ah[0], ah[1], ah[2], ah[3],
                  Wh + (uint32_t)((wm + aRow) * SKC + k0 + aCol) * 2);
            ldsm4(al[0], al[1], al[2], al[3],
                  Wl + (uint32_t)((wm + aRow) * SKC + k0 + aCol) * 2);
            #pragma unroll
            for (int nb = 0; nb < 4; nb++) {
                ldsm4(bh[nb][0], bh[nb][1], bh[nb][2], bh[nb][3],
                      Xh + (uint32_t)((wn + nb * 16 + bRow) * SKC + k0 + bCol) * 2);
                ldsm4(bl[nb][0], bl[nb][1], bl[nb][2], bl[nb][3],
                      Xl + (uint32_t)((wn + nb * 16 + bRow) * SKC + k0 + bCol) * 2);
            }
            #pragma unroll
            for (int nb = 0; nb < 4; nb++) {
                mma_bf16(acc[2 * nb],     ah, bh[nb][0], bh[nb][1]);
                mma_bf16(acc[2 * nb + 1], ah, bh[nb][2], bh[nb][3]);
                mma_bf16(acc[2 * nb],     ah, bl[nb][0], bl[nb][1]);
                mma_bf16(acc[2 * nb + 1], ah, bl[nb][2], bl[nb][3]);
                mma_bf16(acc[2 * nb],     al, bh[nb][0], bh[nb][1]);
                mma_bf16(acc[2 * nb + 1], al, bh[nb][2], bh[nb][3]);
            }
        }

        if (c < 63) STS_W(s ^ 1, vW);
        CP_WAIT0();
        __syncthreads();
    }

    // ---- writeback (each (i,d) owned by exactly one CTA per ksplit half) ----
    int g = lane >> 2, tq = lane & 3;
    #pragma unroll
    for (int nbi = 0; nbi < 8; nbi++) {
        int irow = i0 + wm + g;
        int dcol = wn + nbi * 8 + 2 * tq;
        *(float2*)&g_mx2[((size_t)ks * NN + irow) * UU + dcol] =
            make_float2(acc[nbi][0], acc[nbi][1]);
        *(float2*)&g_mx2[((size_t)ks * NN + irow + 8) * UU + dcol] =
            make_float2(acc[nbi][2], acc[nbi][3]);
    }
}

// ============================================================
// Stage 5: combine halves, normalize, hyperbolic rescale + mobius bias add
// ============================================================
__global__ __launch_bounds__(128) void k_epilogue(const float* __restrict__ bias,
                                                  float* __restrict__ out) {
    __shared__ float sm[4];
    int row = blockIdx.x, t = threadIdx.x;

    float rp = (t < 8) ? g_rsump[row * 8 + t] : 0.f;
    float rs = blockReduce128(rp, sm);

    float m = __fdividef(g_mx2[(size_t)row * UU + t] +
                         g_mx2[(size_t)(NN + row) * UU + t], rs);
    float mn2 = blockReduce128(m * m, sm);
    float x2i = g_x2[row];
    float x_n  = fmaxf(sqrtf(x2i), 1e-15f);
    float mx_n = fmaxf(sqrtf(mn2), 1e-15f);
    float xa   = fminf(x_n, 1.f - 1e-7f);
    float art  = 0.5f * (log1pf(xa) - log1pf(-xa));
    float alpha = __fdividef(tanhf(__fdividef(mx_n, x_n) * art), mx_n);
    float ov = alpha * m;

    float bv  = bias[t];
    float bn2 = blockReduce128(bv * bv, sm);
    float bn  = fmaxf(sqrtf(bn2), 1e-15f);
    float bvx = __fdividef(tanhf(bn), bn) * bv;

    float y2  = blockReduce128(bvx * bvx, sm);
    float xy  = blockReduce128(ov * bvx, sm);
    float x2o = blockReduce128(ov * ov, sm);
    float cx  = 1.f + 2.f * xy + y2;
    float cy  = 1.f - x2o;
    float den = fmaxf(fmaf(x2o, y2, 1.f + 2.f * xy), 1e-15f);
    out[(size_t)row * UU + t] = __fdividef(cx * ov + cy * bvx, den);
}

// ============================================================
extern "C" void kernel_launch(void* const* d_in, const int* in_sizes, int n_in,
                              void* d_out, int out_size) {
    const float* feat = (const float*)d_in[0];
    const int*   adj  = (const int*)  d_in[1];
    const float* W    = (const float*)d_in[2];
    const float* bias = (const float*)d_in[3];
    float* out = (float*)d_out;

    cudaFuncSetAttribute(k_attn, cudaFuncAttributeMaxDynamicSharedMemorySize, G1_SMEM);
    cudaFuncSetAttribute(k_agg,  cudaFuncAttributeMaxDynamicSharedMemorySize, G2_SMEM);

    k_adjmask <<<NN * NN / 32 / 256, 256>>>(adj);
    k_gemmA   <<<NN / 16, 256>>>(feat, W);
    k_expmap  <<<NN, 128>>>();
    k_attn    <<<1024, 256, G1_SMEM>>>();
    k_agg     <<<128, 512, G2_SMEM>>>();
    k_epilogue<<<NN, 128>>>(bias, out);
}

// round 9
// speedup vs baseline: 1.5171x; 1.1289x over previous
#include <cuda_runtime.h>
#include <cuda_bf16.h>
#include <cstdint>
#include <math.h>

#define NN 8192
#define DD 256
#define UU 128

// ================= device scratch (no allocations allowed) =================
__device__ __align__(256) float          g_buf[NN * UU];   // stage1: u = feat@W
__device__ __align__(256) __nv_bfloat16  g_xh[NN * UU];    // bf16 split of x (node-major)
__device__ __align__(256) __nv_bfloat16  g_xl[NN * UU];
__device__ __align__(256) float          g_x2[NN];
__device__ __align__(256) uint32_t       g_adjb[(size_t)NN * NN / 32]; // adjacency bits
__device__ __align__(256) float          g_rsump[NN * 2];  // per (i, j-half) sums
__device__ __align__(256) float          g_mx2[2 * NN * UU]; // j-half slices of mx

// ======================= helpers =======================
__device__ __forceinline__ uint32_t smem_to_u32(const void* p) {
    uint32_t a;
    asm("{ .reg .u64 t; cvta.to.shared.u64 t, %1; cvt.u32.u64 %0, t; }"
        : "=r"(a) : "l"(p));
    return a;
}
__device__ __forceinline__ void cp16(uint32_t saddr, const void* gaddr) {
    asm volatile("cp.async.cg.shared.global [%0], [%1], 16;"
                 :: "r"(saddr), "l"(gaddr));
}
#define CP_COMMIT() asm volatile("cp.async.commit_group;" ::: "memory")
#define CP_WAIT0()  asm volatile("cp.async.wait_group 0;" ::: "memory")

__device__ __forceinline__ void ldsm4(uint32_t& r0, uint32_t& r1, uint32_t& r2,
                                      uint32_t& r3, uint32_t addr) {
    asm volatile("ldmatrix.sync.aligned.m8n8.x4.shared.b16 {%0,%1,%2,%3}, [%4];"
                 : "=r"(r0), "=r"(r1), "=r"(r2), "=r"(r3) : "r"(addr));
}
__device__ __forceinline__ void ldsm4t(uint32_t& r0, uint32_t& r1, uint32_t& r2,
                                       uint32_t& r3, uint32_t addr) {
    asm volatile("ldmatrix.sync.aligned.m8n8.x4.trans.shared.b16 {%0,%1,%2,%3}, [%4];"
                 : "=r"(r0), "=r"(r1), "=r"(r2), "=r"(r3) : "r"(addr));
}
__device__ __forceinline__ void mma_bf16(float* d, const uint32_t* a,
                                         uint32_t b0, uint32_t b1) {
    asm volatile("mma.sync.aligned.m16n8k16.row.col.f32.bf16.bf16.f32 "
                 "{%0,%1,%2,%3}, {%4,%5,%6,%7}, {%8,%9}, {%0,%1,%2,%3};"
                 : "+f"(d[0]), "+f"(d[1]), "+f"(d[2]), "+f"(d[3])
                 : "r"(a[0]), "r"(a[1]), "r"(a[2]), "r"(a[3]), "r"(b0), "r"(b1));
}
__device__ __forceinline__ float fsqrt_fast(float x) {
    float r;
    asm("sqrt.approx.f32 %0, %1;" : "=f"(r) : "f"(x));
    return r;
}

__device__ __forceinline__ float blockReduce128(float v, volatile float* sm) {
    #pragma unroll
    for (int o = 16; o > 0; o >>= 1) v += __shfl_xor_sync(0xffffffffu, v, o);
    if ((threadIdx.x & 31) == 0) sm[threadIdx.x >> 5] = v;
    __syncthreads();
    float r = sm[0] + sm[1] + sm[2] + sm[3];
    __syncthreads();
    return r;
}

// w = exp(hyperbolic distance), closed form; masked by adjacency / dist==0
__device__ __forceinline__ float score_w(float xy, float x2i, float x2j, int am) {
    float A = 1.f - 2.f * xy + x2j;
    float B = 1.f - x2i;
    float num = fmaf(A * A, x2i, fmaf(-2.f * A * B, xy, B * B * x2j));
    num = fmaxf(num, 0.f);
    float den = fmaxf(fmaf(x2i, x2j, 1.f - 2.f * xy), 1e-15f);
    float sq  = fsqrt_fast(num);
    float w;
    if (sq < (1.f - 1e-7f) * den) w = __fdividef(den + sq, den - sq);
    else                          w = (2.f - 1e-7f) / 1e-7f;
    if (am == 0 || !(sq > 0.f)) w = 0.f;
    return w;
}

// ============================================================
// Stage 0: adjacency -> bitmask (1 thread per 32 ints)
// ============================================================
__global__ __launch_bounds__(256) void k_adjmask(const int* __restrict__ adj) {
    size_t w = (size_t)blockIdx.x * 256 + threadIdx.x;
    const int4* p = (const int4*)(adj + w * 32);
    uint32_t m = 0;
    #pragma unroll
    for (int q = 0; q < 8; q++) {
        int4 v = p[q];
        m |= (v.x != 0 ? 1u : 0u) << (q * 4 + 0);
        m |= (v.y != 0 ? 1u : 0u) << (q * 4 + 1);
        m |= (v.z != 0 ? 1u : 0u) << (q * 4 + 2);
        m |= (v.w != 0 ? 1u : 0u) << (q * 4 + 3);
    }
    g_adjb[w] = m;
}

// ============================================================
// Stage 1: u = features @ kernel
// ============================================================
__global__ __launch_bounds__(256) void k_gemmA(const float* __restrict__ feat,
                                               const float* __restrict__ W) {
    __shared__ float fs[16][DD];
    int tid = threadIdx.x;
    int r0  = blockIdx.x * 16;
    for (int idx = tid; idx < 16 * DD; idx += 256)
        fs[idx >> 8][idx & 255] = feat[(size_t)(r0 + (idx >> 8)) * DD + (idx & 255)];
    __syncthreads();
    int col = tid & 127, rg = tid >> 7;
    float acc[8] = {0.f,0.f,0.f,0.f,0.f,0.f,0.f,0.f};
    for (int d = 0; d < DD; d++) {
        float kv = W[d * UU + col];
        #pragma unroll
        for (int r = 0; r < 8; r++)
            acc[r] = fmaf(fs[rg * 8 + r][d], kv, acc[r]);
    }
    #pragma unroll
    for (int r = 0; r < 8; r++)
        g_buf[(size_t)(r0 + rg * 8 + r) * UU + col] = acc[r];
}

// ============================================================
// Stage 2: x = expmap0(u); bf16 hi/lo split (node-major) + x2
// ============================================================
__global__ __launch_bounds__(128) void k_expmap() {
    __shared__ float sm[4];
    int row = blockIdx.x, t = threadIdx.x;
    float v  = g_buf[(size_t)row * UU + t];
    float n2 = blockReduce128(v * v, sm);
    float n  = fmaxf(sqrtf(n2), 1e-15f);
    float xv = tanhf(n) / n * v;

    __nv_bfloat16 bh = __float2bfloat16(xv);
    __nv_bfloat16 bl = __float2bfloat16(xv - __bfloat162float(bh));
    g_xh[(size_t)row * UU + t] = bh;
    g_xl[(size_t)row * UU + t] = bl;

    float s2 = blockReduce128(xv * xv, sm);
    if (t == 0) g_x2[row] = s2;
}

// ============================================================
// Stage 3 (k_fused): scores AND aggregation in one kernel.
// grid 256 = 128 ib x 2 jh; 256 threads; warps 4(m16) x 2(j32).
// Per 64-j chunk: GEMM1 (xy, bf16-split, normal ldsm)
//   -> score epilogue -> w bf16-split packed into A fragments
//   -> GEMM2 O += W * Xj with B via trans-ldsm on the SAME tile.
// No g_w traffic; O register-resident, reduced across warp pairs.
// ============================================================
#define SKA 136
#define AT64 (64 * SKA * 2)            /* 17408 B per 64-row bf16 tile */
#define RS_OFF (6 * AT64)
#define OS_OFF (2 * AT64)              /* O-reduce staging reuses B tiles */
#define G1_SMEM (6 * AT64 + 512)       /* 104960 B */

__device__ __forceinline__ void cp_tile64(char* dst, const __nv_bfloat16* src,
                                          int r0, int tid) {
    #pragma unroll
    for (int it = 0; it < 4; it++) {
        int idx = it * 256 + tid;
        int row = idx >> 4, q = idx & 15;
        cp16(smem_to_u32(dst + (row * SKA + q * 8) * 2),
             (const void*)(src + (size_t)(r0 + row) * UU + q * 8));
    }
}

__global__ __launch_bounds__(256, 2) void k_fused() {
    extern __shared__ char smc[];
    uint32_t sb = smem_to_u32(smc);
    int tid = threadIdx.x, wid = tid >> 5, lane = tid & 31;
    int ib = blockIdx.x >> 1, jh = blockIdx.x & 1;
    int i0 = ib * 64, jbase = jh * 4096;

    int wm = (wid & 3) * 16, wn = (wid >> 2) * 32;
    int g = lane >> 2, tq = lane & 3;
    int aRow = (lane & 7) + ((lane >> 3) & 1) * 8;
    int aCol = (lane >> 4) * 8;
    int bRow = (lane & 7) + (lane >> 4) * 8;
    int bCol = ((lane >> 3) & 1) * 8;
    int tm = lane >> 3, tr = lane & 7;          // trans-ldsm lane mapping

    // prologue: A hi/lo resident + B(c=0) hi/lo
    cp_tile64(smc + 0 * AT64, g_xh, i0, tid);
    cp_tile64(smc + 1 * AT64, g_xl, i0, tid);
    cp_tile64(smc + 2 * AT64, g_xh, jbase, tid);
    cp_tile64(smc + 3 * AT64, g_xl, jbase, tid);
    CP_COMMIT();

    float x2i[2];
    x2i[0] = g_x2[i0 + wm + g];
    x2i[1] = g_x2[i0 + wm + g + 8];

    float rsum[2] = {0.f, 0.f};
    float o[16][4];
    #pragma unroll
    for (int nb = 0; nb < 16; nb++)
        #pragma unroll
        for (int q = 0; q < 4; q++) o[nb][q] = 0.f;

    CP_WAIT0();
    __syncthreads();

    for (int c = 0; c < 64; c++) {
        int s = c & 1;
        if (c < 63) {   // prefetch next 64-row j-tile into the other stage
            int jn = jbase + (c + 1) * 64;
            cp_tile64(smc + (2 + 2 * (s ^ 1)) * AT64, g_xh, jn, tid);
            cp_tile64(smc + (3 + 2 * (s ^ 1)) * AT64, g_xl, jn, tid);
            CP_COMMIT();
        }
        uint32_t Bh = sb + (uint32_t)(2 + 2 * s) * AT64;
        uint32_t Bl = Bh + AT64;

        // ---- GEMM1: xy scores (hh + hl + lh) ----
        float acc[4][4];
        #pragma unroll
        for (int nb = 0; nb < 4; nb++)
            #pragma unroll
            for (int q = 0; q < 4; q++) acc[nb][q] = 0.f;

        uint32_t Ah = sb, Al = sb + AT64;
        #pragma unroll
        for (int ksv = 0; ksv < 8; ksv++) {
            int k0 = ksv * 16;
            uint32_t ah[4], al[4], bh[2][4], bl[2][4];
            ldsm4(ah[0], ah[1], ah[2], ah[3],
                  Ah + (uint32_t)((wm + aRow) * SKA + k0 + aCol) * 2);
            ldsm4(al[0], al[1], al[2], al[3],
                  Al + (uint32_t)((wm + aRow) * SKA + k0 + aCol) * 2);
            #pragma unroll
            for (int nb = 0; nb < 2; nb++) {
                ldsm4(bh[nb][0], bh[nb][1], bh[nb][2], bh[nb][3],
                      Bh + (uint32_t)((wn + nb * 16 + bRow) * SKA + k0 + bCol) * 2);
                ldsm4(bl[nb][0], bl[nb][1], bl[nb][2], bl[nb][3],
                      Bl + (uint32_t)((wn + nb * 16 + bRow) * SKA + k0 + bCol) * 2);
            }
            #pragma unroll
            for (int nb = 0; nb < 2; nb++) {
                mma_bf16(acc[2 * nb],     ah, bh[nb][0], bh[nb][1]);
                mma_bf16(acc[2 * nb + 1], ah, bh[nb][2], bh[nb][3]);
                mma_bf16(acc[2 * nb],     ah, bl[nb][0], bl[nb][1]);
                mma_bf16(acc[2 * nb + 1], ah, bl[nb][2], bl[nb][3]);
                mma_bf16(acc[2 * nb],     al, bh[nb][0], bh[nb][1]);
                mma_bf16(acc[2 * nb + 1], al, bh[nb][2], bh[nb][3]);
            }
        }

        // ---- score epilogue: w -> bf16-split A fragments (registers) ----
        int jc = jbase + c * 64;
        float2 x2jv[4];
        #pragma unroll
        for (int nbi = 0; nbi < 4; nbi++)
            x2jv[nbi] = *(const float2*)&g_x2[jc + wn + nbi * 8 + 2 * tq];

        uint32_t wh[2][4], wl[2][4];
        #pragma unroll
        for (int rh = 0; rh < 2; rh++) {
            int ig = i0 + wm + g + rh * 8;
            uint32_t mword = g_adjb[(size_t)ig * (NN / 32) + ((jc + wn) >> 5)];
            float x2iv = x2i[rh];
            float rs = 0.f;
            #pragma unroll
            for (int nbi = 0; nbi < 4; nbi++) {
                int jl = nbi * 8 + 2 * tq;
                int a0 = (mword >> jl) & 1;
                int a1 = (mword >> (jl + 1)) & 1;
                float w0 = score_w(acc[nbi][rh * 2 + 0], x2iv, x2jv[nbi].x, a0);
                float w1 = score_w(acc[nbi][rh * 2 + 1], x2iv, x2jv[nbi].y, a1);
                rs += w0 + w1;
                __nv_bfloat16 h0 = __float2bfloat16(w0);
                __nv_bfloat16 h1 = __float2bfloat16(w1);
                __nv_bfloat16 l0 = __float2bfloat16(w0 - __bfloat162float(h0));
                __nv_bfloat16 l1 = __float2bfloat16(w1 - __bfloat162float(h1));
                int ks = nbi >> 1, ai = (nbi & 1) * 2 + rh;
                wh[ks][ai] = (uint32_t)__bfloat16_as_ushort(h0)
                           | ((uint32_t)__bfloat16_as_ushort(h1) << 16);
                wl[ks][ai] = (uint32_t)__bfloat16_as_ushort(l0)
                           | ((uint32_t)__bfloat16_as_ushort(l1) << 16);
            }
            rsum[rh] += rs;
        }

        // ---- GEMM2: O += W * Xj  (B via trans-ldsm on the same tiles) ----
        #pragma unroll
        for (int ks = 0; ks < 2; ks++) {
            #pragma unroll
            for (int np = 0; np < 8; np++) {
                uint32_t off = (uint32_t)((wn + ks * 16 + (tm & 1) * 8 + tr) * SKA
                                          + np * 16 + (tm >> 1) * 8) * 2;
                uint32_t bt0, bt1, bt2, bt3, bu0, bu1, bu2, bu3;
                ldsm4t(bt0, bt1, bt2, bt3, Bh + off);
                ldsm4t(bu0, bu1, bu2, bu3, Bl + off);
                mma_bf16(o[np * 2],     wh[ks], bt0, bt1);
                mma_bf16(o[np * 2 + 1], wh[ks], bt2, bt3);
                mma_bf16(o[np * 2],     wh[ks], bu0, bu1);
                mma_bf16(o[np * 2 + 1], wh[ks], bu2, bu3);
                mma_bf16(o[np * 2],     wl[ks], bt0, bt1);
                mma_bf16(o[np * 2 + 1], wl[ks], bt2, bt3);
            }
        }

        if (c < 63) CP_WAIT0();
        __syncthreads();
    }

    // ---- rsum combine + O cross-warp reduction ----
    #pragma unroll
    for (int r = 0; r < 2; r++) {
        rsum[r] += __shfl_xor_sync(0xffffffffu, rsum[r], 1);
        rsum[r] += __shfl_xor_sync(0xffffffffu, rsum[r], 2);
    }
    float* RS = (float*)(smc + RS_OFF);    // [8 warps][16 rows]
    if (tq == 0) {
        RS[wid * 16 + g]     = rsum[0];
        RS[wid * 16 + 8 + g] = rsum[1];
    }
    float* OS = (float*)(smc + OS_OFF);    // 32KB staging (reuses B tiles)
    if (wid >= 4) {
        #pragma unroll
        for (int nb = 0; nb < 16; nb++)
            #pragma unroll
            for (int q = 0; q < 4; q++)
                OS[(wid - 4) * 2048 + (nb * 4 + q) * 32 + lane] = o[nb][q];
    }
    __syncthreads();

    if (tid < 64) {
        int mt = tid >> 4, idx = tid & 15;
        float v = RS[mt * 16 + idx] + RS[(mt + 4) * 16 + idx];
        g_rsump[(i0 + mt * 16 + idx) * 2 + jh] = v;
    }
    if (wid < 4) {
        #pragma unroll
        for (int nb = 0; nb < 16; nb++) {
            float p0 = OS[wid * 2048 + (nb * 4 + 0) * 32 + lane];
            float p1 = OS[wid * 2048 + (nb * 4 + 1) * 32 + lane];
            float p2 = OS[wid * 2048 + (nb * 4 + 2) * 32 + lane];
            float p3 = OS[wid * 2048 + (nb * 4 + 3) * 32 + lane];
            int irow = i0 + wm + g;
            int dcol = nb * 8 + 2 * tq;
            *(float2*)&g_mx2[((size_t)jh * NN + irow) * UU + dcol] =
                make_float2(o[nb][0] + p0, o[nb][1] + p1);
            *(float2*)&g_mx2[((size_t)jh * NN + irow + 8) * UU + dcol] =
                make_float2(o[nb][2] + p2, o[nb][3] + p3);
        }
    }
}

// ============================================================
// Stage 4: combine halves, normalize, hyperbolic rescale + mobius bias add
// ============================================================
__global__ __launch_bounds__(128) void k_epilogue(const float* __restrict__ bias,
                                                  float* __restrict__ out) {
    __shared__ float sm[4];
    int row = blockIdx.x, t = threadIdx.x;

    float rp = (t < 2) ? g_rsump[row * 2 + t] : 0.f;
    float rs = blockReduce128(rp, sm);

    float m = __fdividef(g_mx2[(size_t)row * UU + t] +
                         g_mx2[(size_t)(NN + row) * UU + t], rs);
    float mn2 = blockReduce128(m * m, sm);
    float x2i = g_x2[row];
    float x_n  = fmaxf(sqrtf(x2i), 1e-15f);
    float mx_n = fmaxf(sqrtf(mn2), 1e-15f);
    float xa   = fminf(x_n, 1.f - 1e-7f);
    float art  = 0.5f * (log1pf(xa) - log1pf(-xa));
    float alpha = __fdividef(tanhf(__fdividef(mx_n, x_n) * art), mx_n);
    float ov = alpha * m;

    float bv  = bias[t];
    float bn2 = blockReduce128(bv * bv, sm);
    float bn  = fmaxf(sqrtf(bn2), 1e-15f);
    float bvx = __fdividef(tanhf(bn), bn) * bv;

    float y2  = blockReduce128(bvx * bvx, sm);
    float xy  = blockReduce128(ov * bvx, sm);
    float x2o = blockReduce128(ov * ov, sm);
    float cx  = 1.f + 2.f * xy + y2;
    float cy  = 1.f - x2o;
    float den = fmaxf(fmaf(x2o, y2, 1.f + 2.f * xy), 1e-15f);
    out[(size_t)row * UU + t] = __fdividef(cx * ov + cy * bvx, den);
}

// ============================================================
extern "C" void kernel_launch(void* const* d_in, const int* in_sizes, int n_in,
                              void* d_out, int out_size) {
    const float* feat = (const float*)d_in[0];
    const int*   adj  = (const int*)  d_in[1];
    const float* W    = (const float*)d_in[2];
    const float* bias = (const float*)d_in[3];
    float* out = (float*)d_out;

    cudaFuncSetAttribute(k_fused, cudaFuncAttributeMaxDynamicSharedMemorySize, G1_SMEM);

    k_adjmask <<<NN * NN / 32 / 256, 256>>>(adj);
    k_gemmA   <<<NN / 16, 256>>>(feat, W);
    k_expmap  <<<NN, 128>>>();
    k_fused   <<<256, 256, G1_SMEM>>>();
    k_epilogue<<<NN, 128>>>(bias, out);
}

// round 10
// speedup vs baseline: 1.6516x; 1.0886x over previous
#include <cuda_runtime.h>
#include <cuda_fp16.h>
#include <cstdint>
#include <math.h>

#define NN 8192
#define DD 256
#define UU 128

// ================= device scratch (no allocations allowed) =================
__device__ __align__(256) __half         g_xh[NN * UU];    // fp16 split of x (node-major)
__device__ __align__(256) __half         g_xl[NN * UU];
__device__ __align__(256) float          g_x2[NN];
__device__ __align__(256) uint32_t       g_adjb[(size_t)NN * NN / 32]; // adjacency bits
__device__ __align__(256) float          g_rsump[NN * 2];  // per (i, j-half) sums (scaled)
__device__ __align__(256) float          g_mx2[2 * NN * UU]; // j-half slices of mx (scaled)

// ======================= helpers =======================
__device__ __forceinline__ uint32_t smem_to_u32(const void* p) {
    uint32_t a;
    asm("{ .reg .u64 t; cvta.to.shared.u64 t, %1; cvt.u32.u64 %0, t; }"
        : "=r"(a) : "l"(p));
    return a;
}
__device__ __forceinline__ void cp16(uint32_t saddr, const void* gaddr) {
    asm volatile("cp.async.cg.shared.global [%0], [%1], 16;"
                 :: "r"(saddr), "l"(gaddr));
}
#define CP_COMMIT() asm volatile("cp.async.commit_group;" ::: "memory")
#define CP_WAIT0()  asm volatile("cp.async.wait_group 0;" ::: "memory")

__device__ __forceinline__ void ldsm4(uint32_t& r0, uint32_t& r1, uint32_t& r2,
                                      uint32_t& r3, uint32_t addr) {
    asm volatile("ldmatrix.sync.aligned.m8n8.x4.shared.b16 {%0,%1,%2,%3}, [%4];"
                 : "=r"(r0), "=r"(r1), "=r"(r2), "=r"(r3) : "r"(addr));
}
__device__ __forceinline__ void ldsm4t(uint32_t& r0, uint32_t& r1, uint32_t& r2,
                                       uint32_t& r3, uint32_t addr) {
    asm volatile("ldmatrix.sync.aligned.m8n8.x4.trans.shared.b16 {%0,%1,%2,%3}, [%4];"
                 : "=r"(r0), "=r"(r1), "=r"(r2), "=r"(r3) : "r"(addr));
}
__device__ __forceinline__ void mma_f16(float* d, const uint32_t* a,
                                        uint32_t b0, uint32_t b1) {
    asm volatile("mma.sync.aligned.m16n8k16.row.col.f32.f16.f16.f32 "
                 "{%0,%1,%2,%3}, {%4,%5,%6,%7}, {%8,%9}, {%0,%1,%2,%3};"
                 : "+f"(d[0]), "+f"(d[1]), "+f"(d[2]), "+f"(d[3])
                 : "r"(a[0]), "r"(a[1]), "r"(a[2]), "r"(a[3]), "r"(b0), "r"(b1));
}
__device__ __forceinline__ float fsqrt_fast(float x) {
    float r;
    asm("sqrt.approx.f32 %0, %1;" : "=f"(r) : "f"(x));
    return r;
}
__device__ __forceinline__ uint32_t cvt_f16x2(float hi, float lo) {
    uint32_t r;
    asm("cvt.rn.f16x2.f32 %0, %1, %2;" : "=r"(r) : "f"(hi), "f"(lo));
    return r;
}

__device__ __forceinline__ float blockReduce128(float v, volatile float* sm) {
    #pragma unroll
    for (int o = 16; o > 0; o >>= 1) v += __shfl_xor_sync(0xffffffffu, v, o);
    if ((threadIdx.x & 31) == 0) sm[threadIdx.x >> 5] = v;
    __syncthreads();
    float r = sm[0] + sm[1] + sm[2] + sm[3];
    __syncthreads();
    return r;
}

// w = exp(hyperbolic distance) * 2^-10, closed form; masked by adjacency / dist==0
#define WSC 0.0009765625f
__device__ __forceinline__ float score_w(float xy, float x2i, float x2j, int am) {
    float A = 1.f - 2.f * xy + x2j;
    float B = 1.f - x2i;
    float num = fmaf(A * A, x2i, fmaf(-2.f * A * B, xy, B * B * x2j));
    num = fmaxf(num, 0.f);
    float den = fmaxf(fmaf(x2i, x2j, 1.f - 2.f * xy), 1e-15f);
    float sq  = fsqrt_fast(num);
    float w;
    if (sq < (1.f - 1e-7f) * den) w = __fdividef(den + sq, den - sq) * WSC;
    else                          w = ((2.f - 1e-7f) / 1e-7f) * WSC;
    if (am == 0 || !(sq > 0.f)) w = 0.f;
    return w;
}

// ============================================================
// Stage 0: adjacency -> bitmask (1 thread per 32 ints)
// ============================================================
__global__ __launch_bounds__(256) void k_adjmask(const int* __restrict__ adj) {
    size_t w = (size_t)blockIdx.x * 256 + threadIdx.x;
    const int4* p = (const int4*)(adj + w * 32);
    uint32_t m = 0;
    #pragma unroll
    for (int q = 0; q < 8; q++) {
        int4 v = p[q];
        m |= (v.x != 0 ? 1u : 0u) << (q * 4 + 0);
        m |= (v.y != 0 ? 1u : 0u) << (q * 4 + 1);
        m |= (v.z != 0 ? 1u : 0u) << (q * 4 + 2);
        m |= (v.w != 0 ? 1u : 0u) << (q * 4 + 3);
    }
    g_adjb[w] = m;
}

// ============================================================
// Stage 1 (k_prep): u = feat @ W, then x = expmap0(u) fused.
// 512 blocks x 256 threads, 16 rows per block.
// ============================================================
__global__ __launch_bounds__(256) void k_prep(const float* __restrict__ feat,
                                              const float* __restrict__ W) {
    __shared__ float fs[16][DD];   // 16 KB
    __shared__ float us[16][UU];   // 8 KB
    int tid = threadIdx.x;
    int r0  = blockIdx.x * 16;
    for (int idx = tid; idx < 16 * DD; idx += 256)
        fs[idx >> 8][idx & 255] = feat[(size_t)(r0 + (idx >> 8)) * DD + (idx & 255)];
    __syncthreads();

    int col = tid & 127, rg = tid >> 7;
    float acc[8] = {0.f,0.f,0.f,0.f,0.f,0.f,0.f,0.f};
    for (int d = 0; d < DD; d++) {
        float kv = W[d * UU + col];
        #pragma unroll
        for (int r = 0; r < 8; r++)
            acc[r] = fmaf(fs[rg * 8 + r][d], kv, acc[r]);
    }
    #pragma unroll
    for (int r = 0; r < 8; r++)
        us[rg * 8 + r][col] = acc[r];
    __syncthreads();

    // expmap0 per row: thread owns (row = tid>>4, cols seg*8..seg*8+7)
    int row = tid >> 4, seg = tid & 15;
    float v[8], p2 = 0.f;
    #pragma unroll
    for (int q = 0; q < 8; q++) {
        v[q] = us[row][seg * 8 + q];
        p2 = fmaf(v[q], v[q], p2);
    }
    #pragma unroll
    for (int o = 8; o > 0; o >>= 1)
        p2 += __shfl_xor_sync(0xffffffffu, p2, o);
    float n  = fmaxf(sqrtf(p2), 1e-15f);
    float tn = tanhf(n);
    float fac = tn / n;

    __half2 oh[4], ol[4];
    #pragma unroll
    for (int q = 0; q < 4; q++) {
        float x0 = fac * v[2 * q], x1 = fac * v[2 * q + 1];
        __half h0 = __float2half_rn(x0), h1 = __float2half_rn(x1);
        oh[q] = __halves2half2(h0, h1);
        ol[q] = __halves2half2(__float2half_rn(x0 - __half2float(h0)),
                               __float2half_rn(x1 - __half2float(h1)));
    }
    *(uint4*)&g_xh[(size_t)(r0 + row) * UU + seg * 8] = *(uint4*)oh;
    *(uint4*)&g_xl[(size_t)(r0 + row) * UU + seg * 8] = *(uint4*)ol;
    if (seg == 0) g_x2[r0 + row] = tn * tn;
}

// ============================================================
// Stage 2 (k_fused): scores + aggregation, fp16 HMMA.
// grid 256 = 128 ib x 2 jh; 256 threads; warps 4(m16) x 2(j32).
// GEMM1: 2 products (xh.xh + xh.xl);
// epilogue: w*2^-10 -> fp16 hi/lo A-fragments in registers;
// GEMM2: 3 products (wh.xh + wh.xl + wl.xh), B via trans-ldsm.
// smem: [A_xh][Bh0][Bl0][Bh1][Bl1] + RS  (87.5 KB -> 2 CTA/SM)
// ============================================================
#define SKA 136
#define AT64 (64 * SKA * 2)            /* 17408 B per 64-row fp16 tile */
#define OS_OFF (1 * AT64)              /* O-reduce staging reuses B tiles */
#define RS_OFF (5 * AT64)
#define G1_SMEM (5 * AT64 + 512)       /* 87552 B */

__device__ __forceinline__ void cp_tile64(char* dst, const __half* src,
                                          int r0, int tid) {
    #pragma unroll
    for (int it = 0; it < 4; it++) {
        int idx = it * 256 + tid;
        int row = idx >> 4, q = idx & 15;
        cp16(smem_to_u32(dst + (row * SKA + q * 8) * 2),
             (const void*)(src + (size_t)(r0 + row) * UU + q * 8));
    }
}

__global__ __launch_bounds__(256, 2) void k_fused() {
    extern __shared__ char smc[];
    uint32_t sb = smem_to_u32(smc);
    int tid = threadIdx.x, wid = tid >> 5, lane = tid & 31;
    int ib = blockIdx.x >> 1, jh = blockIdx.x & 1;
    int i0 = ib * 64, jbase = jh * 4096;

    int wm = (wid & 3) * 16, wn = (wid >> 2) * 32;
    int g = lane >> 2, tq = lane & 3;
    int aRow = (lane & 7) + ((lane >> 3) & 1) * 8;
    int aCol = (lane >> 4) * 8;
    int bRow = (lane & 7) + (lane >> 4) * 8;
    int bCol = ((lane >> 3) & 1) * 8;
    int tm = lane >> 3, tr = lane & 7;          // trans-ldsm lane mapping

    // prologue: A xh resident + B(c=0) hi/lo
    cp_tile64(smc + 0 * AT64, g_xh, i0, tid);
    cp_tile64(smc + 1 * AT64, g_xh, jbase, tid);
    cp_tile64(smc + 2 * AT64, g_xl, jbase, tid);
    CP_COMMIT();

    float x2i[2];
    x2i[0] = g_x2[i0 + wm + g];
    x2i[1] = g_x2[i0 + wm + g + 8];

    float rsum[2] = {0.f, 0.f};
    float o[16][4];
    #pragma unroll
    for (int nb = 0; nb < 16; nb++)
        #pragma unroll
        for (int q = 0; q < 4; q++) o[nb][q] = 0.f;

    CP_WAIT0();
    __syncthreads();

    for (int c = 0; c < 64; c++) {
        int s = c & 1;
        if (c < 63) {   // prefetch next 64-row j-tile into the other stage
            int jn = jbase + (c + 1) * 64;
            cp_tile64(smc + (uint32_t)(1 + 2 * (s ^ 1)) * AT64, g_xh, jn, tid);
            cp_tile64(smc + (uint32_t)(2 + 2 * (s ^ 1)) * AT64, g_xl, jn, tid);
            CP_COMMIT();
        }
        uint32_t Bh = sb + (uint32_t)(1 + 2 * s) * AT64;
        uint32_t Bl = Bh + AT64;

        // ---- GEMM1: xy scores, 2 products (hh + hl) ----
        float acc[4][4];
        #pragma unroll
        for (int nb = 0; nb < 4; nb++)
            #pragma unroll
            for (int q = 0; q < 4; q++) acc[nb][q] = 0.f;

        uint32_t Ah = sb;
        #pragma unroll
        for (int ksv = 0; ksv < 8; ksv++) {
            int k0 = ksv * 16;
            uint32_t ah[4], bh[2][4], bl[2][4];
            ldsm4(ah[0], ah[1], ah[2], ah[3],
                  Ah + (uint32_t)((wm + aRow) * SKA + k0 + aCol) * 2);
            #pragma unroll
            for (int nb = 0; nb < 2; nb++) {
                ldsm4(bh[nb][0], bh[nb][1], bh[nb][2], bh[nb][3],
                      Bh + (uint32_t)((wn + nb * 16 + bRow) * SKA + k0 + bCol) * 2);
                ldsm4(bl[nb][0], bl[nb][1], bl[nb][2], bl[nb][3],
                      Bl + (uint32_t)((wn + nb * 16 + bRow) * SKA + k0 + bCol) * 2);
            }
            #pragma unroll
            for (int nb = 0; nb < 2; nb++) {
                mma_f16(acc[2 * nb],     ah, bh[nb][0], bh[nb][1]);
                mma_f16(acc[2 * nb + 1], ah, bh[nb][2], bh[nb][3]);
                mma_f16(acc[2 * nb],     ah, bl[nb][0], bl[nb][1]);
                mma_f16(acc[2 * nb + 1], ah, bl[nb][2], bl[nb][3]);
            }
        }

        // ---- score epilogue: scaled w -> fp16 hi/lo A fragments ----
        int jc = jbase + c * 64;
        float2 x2jv[4];
        #pragma unroll
        for (int nbi = 0; nbi < 4; nbi++)
            x2jv[nbi] = *(const float2*)&g_x2[jc + wn + nbi * 8 + 2 * tq];

        uint32_t wh[2][4], wl[2][4];
        #pragma unroll
        for (int rh = 0; rh < 2; rh++) {
            int ig = i0 + wm + g + rh * 8;
            uint32_t mword = g_adjb[(size_t)ig * (NN / 32) + ((jc + wn) >> 5)];
            float x2iv = x2i[rh];
            float rs = 0.f;
            #pragma unroll
            for (int nbi = 0; nbi < 4; nbi++) {
                int jl = nbi * 8 + 2 * tq;
                int a0 = (mword >> jl) & 1;
                int a1 = (mword >> (jl + 1)) & 1;
                float w0 = score_w(acc[nbi][rh * 2 + 0], x2iv, x2jv[nbi].x, a0);
                float w1 = score_w(acc[nbi][rh * 2 + 1], x2iv, x2jv[nbi].y, a1);
                rs += w0 + w1;
                uint32_t whp = cvt_f16x2(w1, w0);
                __half2 h2 = *reinterpret_cast<__half2*>(&whp);
                uint32_t wlp = cvt_f16x2(w1 - __high2float(h2),
                                         w0 - __low2float(h2));
                int ks = nbi >> 1, ai = (nbi & 1) * 2 + rh;
                wh[ks][ai] = whp;
                wl[ks][ai] = wlp;
            }
            rsum[rh] += rs;
        }

        // ---- GEMM2: O += W * Xj  (B via trans-ldsm on the same tiles) ----
        #pragma unroll
        for (int ks = 0; ks < 2; ks++) {
            #pragma unroll
            for (int np = 0; np < 8; np++) {
                uint32_t off = (uint32_t)((wn + ks * 16 + (tm & 1) * 8 + tr) * SKA
                                          + np * 16 + (tm >> 1) * 8) * 2;
                uint32_t bt0, bt1, bt2, bt3, bu0, bu1, bu2, bu3;
                ldsm4t(bt0, bt1, bt2, bt3, Bh + off);
                ldsm4t(bu0, bu1, bu2, bu3, Bl + off);
                mma_f16(o[np * 2],     wh[ks], bt0, bt1);
                mma_f16(o[np * 2 + 1], wh[ks], bt2, bt3);
                mma_f16(o[np * 2],     wh[ks], bu0, bu1);
                mma_f16(o[np * 2 + 1], wh[ks], bu2, bu3);
                mma_f16(o[np * 2],     wl[ks], bt0, bt1);
                mma_f16(o[np * 2 + 1], wl[ks], bt2, bt3);
            }
        }

        if (c < 63) CP_WAIT0();
        __syncthreads();
    }

    // ---- rsum combine + O cross-warp reduction ----
    #pragma unroll
    for (int r = 0; r < 2; r++) {
        rsum[r] += __shfl_xor_sync(0xffffffffu, rsum[r], 1);
        rsum[r] += __shfl_xor_sync(0xffffffffu, rsum[r], 2);
    }
    float* RS = (float*)(smc + RS_OFF);    // [8 warps][16 rows]
    if (tq == 0) {
        RS[wid * 16 + g]     = rsum[0];
        RS[wid * 16 + 8 + g] = rsum[1];
    }
    float* OS = (float*)(smc + OS_OFF);    // 32KB staging (reuses B tiles)
    if (wid >= 4) {
        #pragma unroll
        for (int nb = 0; nb < 16; nb++)
            #pragma unroll
            for (int q = 0; q < 4; q++)
                OS[(wid - 4) * 2048 + (nb * 4 + q) * 32 + lane] = o[nb][q];
    }
    __syncthreads();

    if (tid < 64) {
        int mt = tid >> 4, idx = tid & 15;
        float v = RS[mt * 16 + idx] + RS[(mt + 4) * 16 + idx];
        g_rsump[(i0 + mt * 16 + idx) * 2 + jh] = v;
    }
    if (wid < 4) {
        #pragma unroll
        for (int nb = 0; nb < 16; nb++) {
            float p0 = OS[wid * 2048 + (nb * 4 + 0) * 32 + lane];
            float p1 = OS[wid * 2048 + (nb * 4 + 1) * 32 + lane];
            float p2 = OS[wid * 2048 + (nb * 4 + 2) * 32 + lane];
            float p3 = OS[wid * 2048 + (nb * 4 + 3) * 32 + lane];
            int irow = i0 + wm + g;
            int dcol = nb * 8 + 2 * tq;
            *(float2*)&g_mx2[((size_t)jh * NN + irow) * UU + dcol] =
                make_float2(o[nb][0] + p0, o[nb][1] + p1);
            *(float2*)&g_mx2[((size_t)jh * NN + irow + 8) * UU + dcol] =
                make_float2(o[nb][2] + p2, o[nb][3] + p3);
        }
    }
}

// ============================================================
// Stage 3: combine halves, normalize, hyperbolic rescale + mobius bias add
// (w-scale 2^-10 cancels in O/rsum)
// ============================================================
__global__ __launch_bounds__(128) void k_epilogue(const float* __restrict__ bias,
                                                  float* __restrict__ out) {
    __shared__ float sm[4];
    int row = blockIdx.x, t = threadIdx.x;

    float rp = (t < 2) ? g_rsump[row * 2 + t] : 0.f;
    float rs = blockReduce128(rp, sm);

    float m = __fdividef(g_mx2[(size_t)row * UU + t] +
                         g_mx2[(size_t)(NN + row) * UU + t], rs);
    float mn2 = blockReduce128(m * m, sm);
    float x2i = g_x2[row];
    float x_n  = fmaxf(sqrtf(x2i), 1e-15f);
    float mx_n = fmaxf(sqrtf(mn2), 1e-15f);
    float xa   = fminf(x_n, 1.f - 1e-7f);
    float art  = 0.5f * (log1pf(xa) - log1pf(-xa));
    float alpha = __fdividef(tanhf(__fdividef(mx_n, x_n) * art), mx_n);
    float ov = alpha * m;

    float bv  = bias[t];
    float bn2 = blockReduce128(bv * bv, sm);
    float bn  = fmaxf(sqrtf(bn2), 1e-15f);
    float bvx = __fdividef(tanhf(bn), bn) * bv;

    float y2  = blockReduce128(bvx * bvx, sm);
    float xy  = blockReduce128(ov * bvx, sm);
    float x2o = blockReduce128(ov * ov, sm);
    float cx  = 1.f + 2.f * xy + y2;
    float cy  = 1.f - x2o;
    float den = fmaxf(fmaf(x2o, y2, 1.f + 2.f * xy), 1e-15f);
    out[(size_t)row * UU + t] = __fdividef(cx * ov + cy * bvx, den);
}

// ============================================================
extern "C" void kernel_launch(void* const* d_in, const int* in_sizes, int n_in,
                              void* d_out, int out_size) {
    const float* feat = (const float*)d_in[0];
    const int*   adj  = (const int*)  d_in[1];
    const float* W    = (const float*)d_in[2];
    const float* bias = (const float*)d_in[3];
    float* out = (float*)d_out;

    cudaFuncSetAttribute(k_fused, cudaFuncAttributeMaxDynamicSharedMemorySize, G1_SMEM);

    k_adjmask <<<NN * NN / 32 / 256, 256>>>(adj);
    k_prep    <<<NN / 16, 256>>>(feat, W);
    k_fused   <<<256, 256, G1_SMEM>>>();
    k_epilogue<<<NN, 128>>>(bias, out);
}

// round 11
// speedup vs baseline: 1.8726x; 1.1339x over previous
#include <cuda_runtime.h>
#include <cuda_fp16.h>
#include <cstdint>
#include <math.h>

#define NN 8192
#define DD 256
#define UU 128

// ================= device scratch (no allocations allowed) =================
__device__ __align__(256) __half         g_xh[NN * UU];    // fp16 split of x (node-major)
__device__ __align__(256) __half         g_xl[NN * UU];
__device__ __align__(256) float          g_x2[NN];
__device__ __align__(256) uint32_t       g_adjb[(size_t)NN * NN / 32]; // adjacency bits
__device__ __align__(256) float          g_rsump[NN * 2];  // per (i, j-half) sums (scaled)
__device__ __align__(256) float          g_mx2[2 * NN * UU]; // j-half slices of mx (scaled)

// ======================= helpers =======================
__device__ __forceinline__ uint32_t smem_to_u32(const void* p) {
    uint32_t a;
    asm("{ .reg .u64 t; cvta.to.shared.u64 t, %1; cvt.u32.u64 %0, t; }"
        : "=r"(a) : "l"(p));
    return a;
}
__device__ __forceinline__ void cp16(uint32_t saddr, const void* gaddr) {
    asm volatile("cp.async.cg.shared.global [%0], [%1], 16;"
                 :: "r"(saddr), "l"(gaddr));
}
#define CP_COMMIT() asm volatile("cp.async.commit_group;" ::: "memory")
#define CP_WAIT0()  asm volatile("cp.async.wait_group 0;" ::: "memory")

__device__ __forceinline__ void ldsm4(uint32_t& r0, uint32_t& r1, uint32_t& r2,
                                      uint32_t& r3, uint32_t addr) {
    asm volatile("ldmatrix.sync.aligned.m8n8.x4.shared.b16 {%0,%1,%2,%3}, [%4];"
                 : "=r"(r0), "=r"(r1), "=r"(r2), "=r"(r3) : "r"(addr));
}
__device__ __forceinline__ void ldsm4t(uint32_t& r0, uint32_t& r1, uint32_t& r2,
                                       uint32_t& r3, uint32_t addr) {
    asm volatile("ldmatrix.sync.aligned.m8n8.x4.trans.shared.b16 {%0,%1,%2,%3}, [%4];"
                 : "=r"(r0), "=r"(r1), "=r"(r2), "=r"(r3) : "r"(addr));
}
__device__ __forceinline__ void mma_f16(float* d, const uint32_t* a,
                                        uint32_t b0, uint32_t b1) {
    asm volatile("mma.sync.aligned.m16n8k16.row.col.f32.f16.f16.f32 "
                 "{%0,%1,%2,%3}, {%4,%5,%6,%7}, {%8,%9}, {%0,%1,%2,%3};"
                 : "+f"(d[0]), "+f"(d[1]), "+f"(d[2]), "+f"(d[3])
                 : "r"(a[0]), "r"(a[1]), "r"(a[2]), "r"(a[3]), "r"(b0), "r"(b1));
}
__device__ __forceinline__ float fsqrt_fast(float x) {
    float r;
    asm("sqrt.approx.f32 %0, %1;" : "=f"(r) : "f"(x));
    return r;
}
__device__ __forceinline__ uint32_t cvt_f16x2(float hi, float lo) {
    uint32_t r;
    asm("cvt.rn.f16x2.f32 %0, %1, %2;" : "=r"(r) : "f"(hi), "f"(lo));
    return r;
}

__device__ __forceinline__ float blockReduce128(float v, volatile float* sm) {
    #pragma unroll
    for (int o = 16; o > 0; o >>= 1) v += __shfl_xor_sync(0xffffffffu, v, o);
    if ((threadIdx.x & 31) == 0) sm[threadIdx.x >> 5] = v;
    __syncthreads();
    float r = sm[0] + sm[1] + sm[2] + sm[3];
    __syncthreads();
    return r;
}

// w = exp(hyperbolic distance) * 2^-10, closed form; masked by adjacency / dist==0
#define WSC 0.0009765625f
__device__ __forceinline__ float score_w(float xy, float x2i, float x2j, int am) {
    float A = 1.f - 2.f * xy + x2j;
    float B = 1.f - x2i;
    float num = fmaf(A * A, x2i, fmaf(-2.f * A * B, xy, B * B * x2j));
    num = fmaxf(num, 0.f);
    float den = fmaxf(fmaf(x2i, x2j, 1.f - 2.f * xy), 1e-15f);
    float sq  = fsqrt_fast(num);
    float w;
    if (sq < (1.f - 1e-7f) * den) w = __fdividef(den + sq, den - sq) * WSC;
    else                          w = ((2.f - 1e-7f) / 1e-7f) * WSC;
    if (am == 0 || !(sq > 0.f)) w = 0.f;
    return w;
}

// ============================================================
// Stage 1 (k_prep): ALL 8192 blocks build the adjacency bitmask;
// blocks < 512 additionally compute u = feat@W and x = expmap0(u).
// Overlaps the two DRAM streams in one launch.
// ============================================================
__global__ __launch_bounds__(256) void k_prep(const float* __restrict__ feat,
                                              const float* __restrict__ W,
                                              const int* __restrict__ adj) {
    __shared__ float fs[16][DD];   // 16 KB
    __shared__ float us[16][UU];   // 8 KB
    int tid = threadIdx.x;

    // ---- adjacency bitmask (1 thread per 32 ints) ----
    {
        size_t w = (size_t)blockIdx.x * 256 + tid;
        const int4* p = (const int4*)(adj + w * 32);
        uint32_t m = 0;
        #pragma unroll
        for (int q = 0; q < 8; q++) {
            int4 v = p[q];
            m |= (v.x != 0 ? 1u : 0u) << (q * 4 + 0);
            m |= (v.y != 0 ? 1u : 0u) << (q * 4 + 1);
            m |= (v.z != 0 ? 1u : 0u) << (q * 4 + 2);
            m |= (v.w != 0 ? 1u : 0u) << (q * 4 + 3);
        }
        g_adjb[w] = m;
    }

    if (blockIdx.x >= NN / 16) return;
    int r0 = blockIdx.x * 16;

    // ---- u = feat @ W (16 rows) ----
    for (int idx = tid; idx < 16 * DD; idx += 256)
        fs[idx >> 8][idx & 255] = feat[(size_t)(r0 + (idx >> 8)) * DD + (idx & 255)];
    __syncthreads();

    int col = tid & 127, rg = tid >> 7;
    float acc[8] = {0.f,0.f,0.f,0.f,0.f,0.f,0.f,0.f};
    for (int d = 0; d < DD; d++) {
        float kv = W[d * UU + col];
        #pragma unroll
        for (int r = 0; r < 8; r++)
            acc[r] = fmaf(fs[rg * 8 + r][d], kv, acc[r]);
    }
    #pragma unroll
    for (int r = 0; r < 8; r++)
        us[rg * 8 + r][col] = acc[r];
    __syncthreads();

    // ---- expmap0 per row (row = tid>>4, cols seg*8..seg*8+7) ----
    int row = tid >> 4, seg = tid & 15;
    float v[8], p2 = 0.f;
    #pragma unroll
    for (int q = 0; q < 8; q++) {
        v[q] = us[row][seg * 8 + q];
        p2 = fmaf(v[q], v[q], p2);
    }
    #pragma unroll
    for (int o = 8; o > 0; o >>= 1)
        p2 += __shfl_xor_sync(0xffffffffu, p2, o);
    float n  = fmaxf(sqrtf(p2), 1e-15f);
    float tn = tanhf(n);
    float fac = tn / n;

    __half2 oh[4], ol[4];
    #pragma unroll
    for (int q = 0; q < 4; q++) {
        float x0 = fac * v[2 * q], x1 = fac * v[2 * q + 1];
        __half h0 = __float2half_rn(x0), h1 = __float2half_rn(x1);
        oh[q] = __halves2half2(h0, h1);
        ol[q] = __halves2half2(__float2half_rn(x0 - __half2float(h0)),
                               __float2half_rn(x1 - __half2float(h1)));
    }
    *(uint4*)&g_xh[(size_t)(r0 + row) * UU + seg * 8] = *(uint4*)oh;
    *(uint4*)&g_xl[(size_t)(r0 + row) * UU + seg * 8] = *(uint4*)ol;
    if (seg == 0) g_x2[r0 + row] = tn * tn;
}

// ============================================================
// Stage 2 (k_fused): scores + aggregation, fp16 HMMA.
// grid 256 = 128 ib x 2 jh; 256 threads; warps 4(m16) x 2(j32).
// GEMM1: 2 products (xh.xh + xh.xl);
// epilogue: w*2^-10 -> fp16 hi/lo A-fragments in registers;
// GEMM2: 2 products (wh.xh + wl.xh), B via trans-ldsm on Bh only.
// smem: [A_xh][Bh0][Bl0][Bh1][Bl1] + RS  (87.5 KB -> 2 CTA/SM)
// ============================================================
#define SKA 136
#define AT64 (64 * SKA * 2)            /* 17408 B per 64-row fp16 tile */
#define OS_OFF (1 * AT64)              /* O-reduce staging reuses B tiles */
#define RS_OFF (5 * AT64)
#define G1_SMEM (5 * AT64 + 512)       /* 87552 B */

__device__ __forceinline__ void cp_tile64(char* dst, const __half* src,
                                          int r0, int tid) {
    #pragma unroll
    for (int it = 0; it < 4; it++) {
        int idx = it * 256 + tid;
        int row = idx >> 4, q = idx & 15;
        cp16(smem_to_u32(dst + (row * SKA + q * 8) * 2),
             (const void*)(src + (size_t)(r0 + row) * UU + q * 8));
    }
}

__global__ __launch_bounds__(256, 2) void k_fused() {
    extern __shared__ char smc[];
    uint32_t sb = smem_to_u32(smc);
    int tid = threadIdx.x, wid = tid >> 5, lane = tid & 31;
    int ib = blockIdx.x >> 1, jh = blockIdx.x & 1;
    int i0 = ib * 64, jbase = jh * 4096;

    int wm = (wid & 3) * 16, wn = (wid >> 2) * 32;
    int g = lane >> 2, tq = lane & 3;
    int aRow = (lane & 7) + ((lane >> 3) & 1) * 8;
    int aCol = (lane >> 4) * 8;
    int bRow = (lane & 7) + (lane >> 4) * 8;
    int bCol = ((lane >> 3) & 1) * 8;
    int tm = lane >> 3, tr = lane & 7;          // trans-ldsm lane mapping

    // prologue: A xh resident + B(c=0) hi/lo
    cp_tile64(smc + 0 * AT64, g_xh, i0, tid);
    cp_tile64(smc + 1 * AT64, g_xh, jbase, tid);
    cp_tile64(smc + 2 * AT64, g_xl, jbase, tid);
    CP_COMMIT();

    float x2i[2];
    x2i[0] = g_x2[i0 + wm + g];
    x2i[1] = g_x2[i0 + wm + g + 8];

    float rsum[2] = {0.f, 0.f};
    float o[16][4];
    #pragma unroll
    for (int nb = 0; nb < 16; nb++)
        #pragma unroll
        for (int q = 0; q < 4; q++) o[nb][q] = 0.f;

    CP_WAIT0();
    __syncthreads();

    for (int c = 0; c < 64; c++) {
        int s = c & 1;
        if (c < 63) {   // prefetch next 64-row j-tile into the other stage
            int jn = jbase + (c + 1) * 64;
            cp_tile64(smc + (uint32_t)(1 + 2 * (s ^ 1)) * AT64, g_xh, jn, tid);
            cp_tile64(smc + (uint32_t)(2 + 2 * (s ^ 1)) * AT64, g_xl, jn, tid);
            CP_COMMIT();
        }
        uint32_t Bh = sb + (uint32_t)(1 + 2 * s) * AT64;
        uint32_t Bl = Bh + AT64;

        // ---- GEMM1: xy scores, 2 products (hh + hl) ----
        float acc[4][4];
        #pragma unroll
        for (int nb = 0; nb < 4; nb++)
            #pragma unroll
            for (int q = 0; q < 4; q++) acc[nb][q] = 0.f;

        uint32_t Ah = sb;
        #pragma unroll
        for (int ksv = 0; ksv < 8; ksv++) {
            int k0 = ksv * 16;
            uint32_t ah[4], bh[2][4], bl[2][4];
            ldsm4(ah[0], ah[1], ah[2], ah[3],
                  Ah + (uint32_t)((wm + aRow) * SKA + k0 + aCol) * 2);
            #pragma unroll
            for (int nb = 0; nb < 2; nb++) {
                ldsm4(bh[nb][0], bh[nb][1], bh[nb][2], bh[nb][3],
                      Bh + (uint32_t)((wn + nb * 16 + bRow) * SKA + k0 + bCol) * 2);
                ldsm4(bl[nb][0], bl[nb][1], bl[nb][2], bl[nb][3],
                      Bl + (uint32_t)((wn + nb * 16 + bRow) * SKA + k0 + bCol) * 2);
            }
            #pragma unroll
            for (int nb = 0; nb < 2; nb++) {
                mma_f16(acc[2 * nb],     ah, bh[nb][0], bh[nb][1]);
                mma_f16(acc[2 * nb + 1], ah, bh[nb][2], bh[nb][3]);
                mma_f16(acc[2 * nb],     ah, bl[nb][0], bl[nb][1]);
                mma_f16(acc[2 * nb + 1], ah, bl[nb][2], bl[nb][3]);
            }
        }

        // ---- score epilogue: scaled w -> fp16 hi/lo A fragments ----
        int jc = jbase + c * 64;
        float2 x2jv[4];
        #pragma unroll
        for (int nbi = 0; nbi < 4; nbi++)
            x2jv[nbi] = *(const float2*)&g_x2[jc + wn + nbi * 8 + 2 * tq];

        uint32_t wh[2][4], wl[2][4];
        #pragma unroll
        for (int rh = 0; rh < 2; rh++) {
            int ig = i0 + wm + g + rh * 8;
            uint32_t mword = g_adjb[(size_t)ig * (NN / 32) + ((jc + wn) >> 5)];
            float x2iv = x2i[rh];
            float rs = 0.f;
            #pragma unroll
            for (int nbi = 0; nbi < 4; nbi++) {
                int jl = nbi * 8 + 2 * tq;
                int a0 = (mword >> jl) & 1;
                int a1 = (mword >> (jl + 1)) & 1;
                float w0 = score_w(acc[nbi][rh * 2 + 0], x2iv, x2jv[nbi].x, a0);
                float w1 = score_w(acc[nbi][rh * 2 + 1], x2iv, x2jv[nbi].y, a1);
                rs += w0 + w1;
                uint32_t whp = cvt_f16x2(w1, w0);
                __half2 h2 = *reinterpret_cast<__half2*>(&whp);
                uint32_t wlp = cvt_f16x2(w1 - __high2float(h2),
                                         w0 - __low2float(h2));
                int ks = nbi >> 1, ai = (nbi & 1) * 2 + rh;
                wh[ks][ai] = whp;
                wl[ks][ai] = wlp;
            }
            rsum[rh] += rs;
        }

        // ---- GEMM2: O += W * Xj  (Bh trans-ldsm only; wh + wl products) ----
        #pragma unroll
        for (int ks = 0; ks < 2; ks++) {
            #pragma unroll
            for (int np = 0; np < 8; np++) {
                uint32_t off = (uint32_t)((wn + ks * 16 + (tm & 1) * 8 + tr) * SKA
                                          + np * 16 + (tm >> 1) * 8) * 2;
                uint32_t bt0, bt1, bt2, bt3;
                ldsm4t(bt0, bt1, bt2, bt3, Bh + off);
                mma_f16(o[np * 2],     wh[ks], bt0, bt1);
                mma_f16(o[np * 2 + 1], wh[ks], bt2, bt3);
                mma_f16(o[np * 2],     wl[ks], bt0, bt1);
                mma_f16(o[np * 2 + 1], wl[ks], bt2, bt3);
            }
        }

        if (c < 63) CP_WAIT0();
        __syncthreads();
    }

    // ---- rsum combine + O cross-warp reduction ----
    #pragma unroll
    for (int r = 0; r < 2; r++) {
        rsum[r] += __shfl_xor_sync(0xffffffffu, rsum[r], 1);
        rsum[r] += __shfl_xor_sync(0xffffffffu, rsum[r], 2);
    }
    float* RS = (float*)(smc + RS_OFF);    // [8 warps][16 rows]
    if (tq == 0) {
        RS[wid * 16 + g]     = rsum[0];
        RS[wid * 16 + 8 + g] = rsum[1];
    }
    float* OS = (float*)(smc + OS_OFF);    // 32KB staging (reuses B tiles)
    if (wid >= 4) {
        #pragma unroll
        for (int nb = 0; nb < 16; nb++)
            #pragma unroll
            for (int q = 0; q < 4; q++)
                OS[(wid - 4) * 2048 + (nb * 4 + q) * 32 + lane] = o[nb][q];
    }
    __syncthreads();

    if (tid < 64) {
        int mt = tid >> 4, idx = tid & 15;
        float v = RS[mt * 16 + idx] + RS[(mt + 4) * 16 + idx];
        g_rsump[(i0 + mt * 16 + idx) * 2 + jh] = v;
    }
    if (wid < 4) {
        #pragma unroll
        for (int nb = 0; nb < 16; nb++) {
            float p0 = OS[wid * 2048 + (nb * 4 + 0) * 32 + lane];
            float p1 = OS[wid * 2048 + (nb * 4 + 1) * 32 + lane];
            float p2 = OS[wid * 2048 + (nb * 4 + 2) * 32 + lane];
            float p3 = OS[wid * 2048 + (nb * 4 + 3) * 32 + lane];
            int irow = i0 + wm + g;
            int dcol = nb * 8 + 2 * tq;
            *(float2*)&g_mx2[((size_t)jh * NN + irow) * UU + dcol] =
                make_float2(o[nb][0] + p0, o[nb][1] + p1);
            *(float2*)&g_mx2[((size_t)jh * NN + irow + 8) * UU + dcol] =
                make_float2(o[nb][2] + p2, o[nb][3] + p3);
        }
    }
}

// ============================================================
// Stage 3: combine halves, normalize, hyperbolic rescale + mobius bias add
// (w-scale 2^-10 cancels in O/rsum)
// ============================================================
__global__ __launch_bounds__(128) void k_epilogue(const float* __restrict__ bias,
                                                  float* __restrict__ out) {
    __shared__ float sm[4];
    int row = blockIdx.x, t = threadIdx.x;

    float rp = (t < 2) ? g_rsump[row * 2 + t] : 0.f;
    float rs = blockReduce128(rp, sm);

    float m = __fdividef(g_mx2[(size_t)row * UU + t] +
                         g_mx2[(size_t)(NN + row) * UU + t], rs);
    float mn2 = blockReduce128(m * m, sm);
    float x2i = g_x2[row];
    float x_n  = fmaxf(sqrtf(x2i), 1e-15f);
    float mx_n = fmaxf(sqrtf(mn2), 1e-15f);
    float xa   = fminf(x_n, 1.f - 1e-7f);
    float art  = 0.5f * (log1pf(xa) - log1pf(-xa));
    float alpha = __fdividef(tanhf(__fdividef(mx_n, x_n) * art), mx_n);
    float ov = alpha * m;

    float bv  = bias[t];
    float bn2 = blockReduce128(bv * bv, sm);
    float bn  = fmaxf(sqrtf(bn2), 1e-15f);
    float bvx = __fdividef(tanhf(bn), bn) * bv;

    float y2  = blockReduce128(bvx * bvx, sm);
    float xy  = blockReduce128(ov * bvx, sm);
    float x2o = blockReduce128(ov * ov, sm);
    float cx  = 1.f + 2.f * xy + y2;
    float cy  = 1.f - x2o;
    float den = fmaxf(fmaf(x2o, y2, 1.f + 2.f * xy), 1e-15f);
    out[(size_t)row * UU + t] = __fdividef(cx * ov + cy * bvx, den);
}

// ============================================================
extern "C" void kernel_launch(void* const* d_in, const int* in_sizes, int n_in,
                              void* d_out, int out_size) {
    const float* feat = (const float*)d_in[0];
    const int*   adj  = (const int*)  d_in[1];
    const float* W    = (const float*)d_in[2];
    const float* bias = (const float*)d_in[3];
    float* out = (float*)d_out;

    cudaFuncSetAttribute(k_fused, cudaFuncAttributeMaxDynamicSharedMemorySize, G1_SMEM);

    k_prep    <<<NN * NN / 32 / 256, 256>>>(feat, W, adj);
    k_fused   <<<256, 256, G1_SMEM>>>();
    k_epilogue<<<NN, 128>>>(bias, out);
}